// round 10
// baseline (speedup 1.0000x reference)
#include <cuda_runtime.h>

#define TT    128
#define HORZ  24
#define LOG2E 1.44269504f

typedef unsigned long long u64;

// ---------------- global scratch (sanctioned __device__ arrays) ----------------
__device__ float g_H [4096 * TT * 64];   // H[b][t][j]  (h_t at row t)  134 MB
__device__ float g_Hp[4096 * TT * 32];   // Hp[b][t][a]                 67 MB
__device__ float g_d0[4096 * 64];        // d0[b][j]                     1 MB

// ---------------- device helpers ----------------
__device__ __forceinline__ void fma2(u64 &acc, u64 w, u64 h){
    asm("fma.rn.f32x2 %0, %1, %2, %0;" : "+l"(acc) : "l"(w), "l"(h));
}
__device__ __forceinline__ float hsum2(u64 a){
    return __uint_as_float((unsigned)a) + __uint_as_float((unsigned)(a >> 32));
}
__device__ __forceinline__ float ex2f(float x){ float y; asm("ex2.approx.f32 %0, %1;" : "=f"(y) : "f"(x)); return y; }
__device__ __forceinline__ float rcpf(float x){ float y; asm("rcp.approx.f32 %0, %1;" : "=f"(y) : "f"(x)); return y; }
__device__ __forceinline__ float sigm(float x){ return rcpf(1.0f + ex2f(-LOG2E * x)); }
__device__ __forceinline__ float tanh_acc(float x){
    float xx = fminf(15.0f, fmaxf(-15.0f, x));
    float e  = ex2f(2.0f * LOG2E * xx);
    return (e - 1.0f) * rcpf(e + 1.0f);
}
__device__ __forceinline__ float tanh_fast(float x){
    float y; asm("tanh.approx.f32 %0, %1;" : "=f"(y) : "f"(x)); return y;
}

// ================= KERNEL 1: encoder (per-b CTA, 1 barrier/step) ==============
#define K1_H     0                       // 129 x 64 (row 0 = h_{-1} = 0)
#define K1_HP    (K1_H + 129*64)         // 128 x 33
#define K1_XS    (K1_HP + 128*33)        // 128
#define K1_DBUF  (K1_XS + 128)           // 64
#define K1_PR    (K1_DBUF + 64)          // 128
#define K1_FLOATS (K1_PR + 128)
#define K1_BYTES  (K1_FLOATS * 4)        // 51.2 KB -> 4 CTAs/SM

extern "C" __global__ void __launch_bounds__(128, 4)
darnn_enc_pb(const float* __restrict__ x,
             const float* __restrict__ W_ih_e, const float* __restrict__ W_hh_e,
             const float* __restrict__ b_ih_e, const float* __restrict__ b_hh_e,
             const float* __restrict__ W_init, const float* __restrict__ b_init,
             const float* __restrict__ U_d)
{
    extern __shared__ __align__(16) float sm[];
    float* H    = sm + K1_H;
    float* Hp   = sm + K1_HP;
    float* xs   = sm + K1_XS;
    float* dbuf = sm + K1_DBUF;
    float* pR   = sm + K1_PR;

    const int tid  = threadIdx.x;
    const int b    = blockIdx.x;
    const int lane = tid & 31;
    const int warp = tid >> 5;
    // GRU mapping: pair-split k across adjacent lanes
    const int jj  = warp * 16 + (lane >> 1);   // output unit 0..63
    const int kh  = lane & 1;                  // k-half

    // ---- encoder GRU weights: 3 half-rows (16 u64 each)
    u64 wr[16], wz[16], wn[16];
    {
        const u64* Wr = (const u64*)(W_hh_e + (jj)       * 64 + kh * 32);
        const u64* Wz = (const u64*)(W_hh_e + (64 + jj)  * 64 + kh * 32);
        const u64* Wn = (const u64*)(W_hh_e + (128 + jj) * 64 + kh * 32);
        #pragma unroll
        for (int k = 0; k < 16; k++){ wr[k] = Wr[k]; wz[k] = Wz[k]; wn[k] = Wn[k]; }
    }
    const float wih_r = W_ih_e[jj], wih_z = W_ih_e[64 + jj], wih_n = W_ih_e[128 + jj];
    const float br  = b_ih_e[jj]       + b_hh_e[jj];
    const float bz  = b_ih_e[64 + jj]  + b_hh_e[64 + jj];
    const float bin = b_ih_e[128 + jj];
    const float bhn = b_hh_e[128 + jj];

    xs[tid] = x[(size_t)b * TT + tid];
    if (tid < 64) H[tid] = 0.0f;
    __syncthreads();

    // ---- encoder: 128 GRU steps, ONE barrier per step
    float hcur = 0.0f;
    for (int t = 0; t < TT; t++){
        const ulonglong2* hp2 = (const ulonglong2*)(H + t * 64 + kh * 32);
        u64 ar = 0ULL, az = 0ULL, an = 0ULL;
        #pragma unroll
        for (int k = 0; k < 8; k++){
            ulonglong2 h2 = hp2[k];
            fma2(ar, wr[2*k], h2.x); fma2(ar, wr[2*k+1], h2.y);
            fma2(az, wz[2*k], h2.x); fma2(az, wz[2*k+1], h2.y);
            fma2(an, wn[2*k], h2.x); fma2(an, wn[2*k+1], h2.y);
        }
        float sr = hsum2(ar); sr += __shfl_xor_sync(0xffffffffu, sr, 1);
        float sz = hsum2(az); sz += __shfl_xor_sync(0xffffffffu, sz, 1);
        float sn = hsum2(an); sn += __shfl_xor_sync(0xffffffffu, sn, 1);
        float xt = xs[t];
        float r  = sigm(fmaf(xt, wih_r, br) + sr);
        float z  = sigm(fmaf(xt, wih_z, bz) + sz);
        float n  = tanh_acc(fmaf(xt, wih_n, bin) + r * (sn + bhn));
        hcur = n + z * (hcur - n);
        H[(t + 1) * 64 + jj] = hcur;          // both kh lanes write same value
        __syncthreads();
    }

    // ---- H_proj pass: warp owns 32 t's, lane = a (verbatim R9)
    {
        u64 ud[32];
        const u64* U = (const u64*)(U_d + lane * 64);
        #pragma unroll
        for (int k = 0; k < 32; k++) ud[k] = U[k];
        for (int tt = 0; tt < 32; tt++){
            int t = warp * 32 + tt;
            const float* hrow = H + (t + 1) * 64;
            u64 acc = 0ULL;
            #pragma unroll
            for (int k = 0; k < 16; k++){
                ulonglong2 h2 = *(const ulonglong2*)(hrow + k * 4);
                fma2(acc, ud[2*k], h2.x); fma2(acc, ud[2*k+1], h2.y);
            }
            Hp[t * 33 + lane] = hsum2(acc);
        }
    }

    // ---- d0 = W_init . h_T + b_init (k-split via pR, as R9)
    {
        const int j2  = ((warp >> 1) << 5) + lane;
        const int kh2 = warp & 1;
        const ulonglong2* Wi = (const ulonglong2*)(W_init + j2 * 64 + kh2 * 32);
        const float* hT = H + TT * 64 + kh2 * 32;
        u64 acc = 0ULL;
        #pragma unroll
        for (int k = 0; k < 8; k++){
            ulonglong2 h2 = *(const ulonglong2*)(hT + k * 4);
            ulonglong2 w2 = Wi[k];
            fma2(acc, w2.x, h2.x); fma2(acc, w2.y, h2.y);
        }
        pR[kh2 * 64 + j2] = hsum2(acc);
        __syncthreads();
        if (kh2 == 0) dbuf[j2] = pR[j2] + pR[64 + j2] + b_init[j2];
    }
    __syncthreads();

    // ---- dump to global scratch (verbatim R9)
    {
        const float4* srcH = (const float4*)(H + 64);        // rows 1..128 = h_0..h_127
        float4* dstH = (float4*)(g_H + (size_t)b * (TT * 64));
        for (int i = tid; i < TT * 64 / 4; i += 128) dstH[i] = srcH[i];
        float* dstHp = g_Hp + (size_t)b * (TT * 32);
        for (int i = tid; i < TT * 32; i += 128){
            int tt = i >> 5, a = i & 31;
            dstHp[i] = Hp[tt * 33 + a];
        }
        if (tid < 64) g_d0[(size_t)b * 64 + tid] = dbuf[tid];
    }
}

// ================= KERNEL 2: decoder (2 barriers/step, ctx via q-trick) =======
#define DSM_HP    0                      // 128 x 33
#define DSM_QV    (DSM_HP + 128*33)      // 128   q_t = <wout_c, h_t>
#define DSM_DBUF  (DSM_QV + 128)         // 2 x 64
#define DSM_WD    (DSM_DBUF + 128)       // 32 x 64
#define DSM_WC    (DSM_WD + 2048)        // 64
#define DSM_VD    (DSM_WC + 64)          // 32
#define DSM_RED   (DSM_VD + 32)          // 8
#define DSM_FLOATS (DSM_RED + 8)
#define DSM_BYTES  (DSM_FLOATS * 4)      // 26.5 KB

extern "C" __global__ void __launch_bounds__(128, 4)
darnn_decoder(const float* __restrict__ W_ih_d, const float* __restrict__ W_hh_d,
              const float* __restrict__ b_ih_d, const float* __restrict__ b_hh_d,
              const float* __restrict__ W_d,    const float* __restrict__ v_d,
              const float* __restrict__ W_out,  const float* __restrict__ b_out,
              const float* __restrict__ y0,
              float* __restrict__ out)
{
    extern __shared__ __align__(16) float sm[];
    float* Hps  = sm + DSM_HP;
    float* qv   = sm + DSM_QV;
    float* dbuf = sm + DSM_DBUF;
    float* sWd  = sm + DSM_WD;
    float* wc   = sm + DSM_WC;
    float* vd   = sm + DSM_VD;
    float* red  = sm + DSM_RED;

    const int tid  = threadIdx.x;
    const int b    = blockIdx.x;
    const int lane = tid & 31;
    const int warp = tid >> 5;
    const int jj   = warp * 16 + (lane >> 1);  // GRU output unit
    const int kh   = lane & 1;                 // k-half

    // ---- stage Hp, W_d, wc, vd
    {
        const float* gHp = g_Hp + (size_t)b * (TT * 32);
        for (int i = tid; i < TT * 32; i += 128){
            int tt = i >> 5, a = i & 31;
            Hps[tt * 33 + a] = gHp[i];
        }
        for (int i = tid; i < 2048 / 4; i += 128)
            ((float4*)sWd)[i] = ((const float4*)W_d)[i];
        if (tid < 64) wc[tid] = W_out[64 + tid];
        if (tid < 32) vd[tid] = v_d[tid];
    }
    __syncthreads();                                   // wc visible for q

    // ---- q_t = <wout_c, h_t> : thread tid = t, read g_H row, wc broadcast
    {
        const ulonglong2* hrow = (const ulonglong2*)(g_H + (size_t)b * (TT * 64) + tid * 64);
        const ulonglong2* wcp  = (const ulonglong2*)wc;
        u64 acc = 0ULL;
        #pragma unroll
        for (int k = 0; k < 16; k++){
            ulonglong2 h2 = hrow[k];
            ulonglong2 w2 = wcp[k];
            fma2(acc, w2.x, h2.x); fma2(acc, w2.y, h2.y);
        }
        qv[tid] = hsum2(acc);
    }

    // ---- decoder GRU weights (pair-split)
    u64 wr[16], wz[16], wn[16];
    {
        const u64* Wr = (const u64*)(W_hh_d + (jj)       * 64 + kh * 32);
        const u64* Wz = (const u64*)(W_hh_d + (64 + jj)  * 64 + kh * 32);
        const u64* Wn = (const u64*)(W_hh_d + (128 + jj) * 64 + kh * 32);
        #pragma unroll
        for (int k = 0; k < 16; k++){ wr[k] = Wr[k]; wz[k] = Wz[k]; wn[k] = Wn[k]; }
    }
    const float wih_r = W_ih_d[jj], wih_z = W_ih_d[64 + jj], wih_n = W_ih_d[128 + jj];
    const float br  = b_ih_d[jj]      + b_hh_d[jj];
    const float bz  = b_ih_d[64 + jj] + b_hh_d[64 + jj];
    const float bin = b_ih_d[128 + jj];
    const float bhn = b_hh_d[128 + jj];
    const float wd0 = W_out[lane], wd1 = W_out[32 + lane];   // for wsum_d
    const float bo  = b_out[0];
    float xdec = y0[0];

    float dj = g_d0[(size_t)b * 64 + jj];
    dbuf[jj] = dj;                                     // buffer 0 (redundant pair write)
    __syncthreads();                                   // qv + dbuf visible

    // ---- 24 decoder steps, TWO barriers each
    for (int s = 0; s < HORZ; s++){
        const float* drow   = dbuf + (s & 1) * 64;
        float*       drow_n = dbuf + ((s + 1) & 1) * 64;

        // GRU (pair-split, shfl combine)
        {
            const ulonglong2* dp2 = (const ulonglong2*)(drow + kh * 32);
            u64 ar = 0ULL, az = 0ULL, an = 0ULL;
            #pragma unroll
            for (int k = 0; k < 8; k++){
                ulonglong2 h2 = dp2[k];
                fma2(ar, wr[2*k], h2.x); fma2(ar, wr[2*k+1], h2.y);
                fma2(az, wz[2*k], h2.x); fma2(az, wz[2*k+1], h2.y);
                fma2(an, wn[2*k], h2.x); fma2(an, wn[2*k+1], h2.y);
            }
            float sr = hsum2(ar); sr += __shfl_xor_sync(0xffffffffu, sr, 1);
            float sz = hsum2(az); sz += __shfl_xor_sync(0xffffffffu, sz, 1);
            float sn = hsum2(an); sn += __shfl_xor_sync(0xffffffffu, sn, 1);
            float r  = sigm(fmaf(xdec, wih_r, br) + sr);
            float z  = sigm(fmaf(xdec, wih_z, bz) + sz);
            float n  = tanh_acc(fmaf(xdec, wih_n, bin) + r * (sn + bhn));
            dj = n + z * (dj - n);
            drow_n[jj] = dj;                           // redundant pair write
        }
        __syncthreads();                               // B1: d_new visible

        // wsum_d = <wout_d, d_new>  (per-warp redundant, butterfly reduce)
        float wsum;
        {
            float dn0 = drow_n[lane], dn1 = drow_n[32 + lane];
            wsum = fmaf(wd0, dn0, wd1 * dn1);
            #pragma unroll
            for (int o = 16; o > 0; o >>= 1) wsum += __shfl_xor_sync(0xffffffffu, wsum, o);
        }

        // d_proj: lane = a, full 64-dot (per-warp redundant, dpv stays in lane regs)
        float dpv;
        {
            const ulonglong2* wrow = (const ulonglong2*)(sWd + lane * 64);
            const ulonglong2* dsrc = (const ulonglong2*)drow_n;
            u64 acc = 0ULL;
            #pragma unroll
            for (int k = 0; k < 16; k++){
                ulonglong2 w2 = wrow[k];
                ulonglong2 d2 = dsrc[k];
                fma2(acc, w2.x, d2.x); fma2(acc, w2.y, d2.y);
            }
            dpv = hsum2(acc);
        }

        // scores: thread tid = t; dpv[a] via shfl; e_t and e_t*q_t reduced together
        {
            const float* hpt = Hps + tid * 33;
            float sc0 = 0.0f, sc1 = 0.0f;
            #pragma unroll
            for (int a = 0; a < 32; a += 2){
                float dpa0 = __shfl_sync(0xffffffffu, dpv, a);
                float dpa1 = __shfl_sync(0xffffffffu, dpv, a + 1);
                sc0 = fmaf(vd[a],     tanh_fast(dpa0 + hpt[a]),     sc0);
                sc1 = fmaf(vd[a + 1], tanh_fast(dpa1 + hpt[a + 1]), sc1);
            }
            float e  = ex2f((sc0 + sc1) * LOG2E);      // softmax w/o max (bounded scores)
            float eq = e * qv[tid];
            #pragma unroll
            for (int o = 16; o > 0; o >>= 1){
                e  += __shfl_xor_sync(0xffffffffu, e,  o);
                eq += __shfl_xor_sync(0xffffffffu, eq, o);
            }
            if (lane == 0){ red[warp * 2] = e; red[warp * 2 + 1] = eq; }
        }
        __syncthreads();                               // B2: warp sums visible

        float esum = (red[0] + red[2]) + (red[4] + red[6]);
        float eqs  = (red[1] + red[3]) + (red[5] + red[7]);
        float val  = wsum + bo + eqs * rcpf(esum);
        if (tid == 0) out[b * HORZ + s] = val;
        xdec = val;
    }
}

extern "C" void kernel_launch(void* const* d_in, const int* in_sizes, int n_in,
                              void* d_out, int out_size)
{
    (void)in_sizes; (void)n_in; (void)out_size;
    const float* x      = (const float*)d_in[0];
    const float* W_ih_e = (const float*)d_in[1];
    const float* W_hh_e = (const float*)d_in[2];
    const float* b_ih_e = (const float*)d_in[3];
    const float* b_hh_e = (const float*)d_in[4];
    // d_in[5..8] dead (encoder input attention == softmax over singleton axis)
    const float* W_init = (const float*)d_in[9];
    const float* b_init = (const float*)d_in[10];
    const float* W_ih_d = (const float*)d_in[11];
    const float* W_hh_d = (const float*)d_in[12];
    const float* b_ih_d = (const float*)d_in[13];
    const float* b_hh_d = (const float*)d_in[14];
    const float* W_d    = (const float*)d_in[15];
    const float* U_d    = (const float*)d_in[16];
    const float* v_d    = (const float*)d_in[17];
    const float* W_out  = (const float*)d_in[18];
    const float* b_out  = (const float*)d_in[19];
    const float* y0     = (const float*)d_in[20];
    float* out = (float*)d_out;

    cudaFuncSetAttribute(darnn_enc_pb,  cudaFuncAttributeMaxDynamicSharedMemorySize, K1_BYTES);
    cudaFuncSetAttribute(darnn_decoder, cudaFuncAttributeMaxDynamicSharedMemorySize, DSM_BYTES);

    darnn_enc_pb<<<4096, 128, K1_BYTES>>>(x, W_ih_e, W_hh_e, b_ih_e, b_hh_e,
                                          W_init, b_init, U_d);
    darnn_decoder<<<4096, 128, DSM_BYTES>>>(W_ih_d, W_hh_d, b_ih_d, b_hh_d,
                                            W_d, v_d, W_out, b_out, y0, out);
}

// round 11
// speedup vs baseline: 1.4530x; 1.4530x over previous
#include <cuda_runtime.h>

#define TT    128
#define HORZ  24
#define LOG2E 1.44269504f

typedef unsigned long long u64;

// ---------------- global scratch (sanctioned __device__ arrays) ----------------
__device__ float g_H [4096 * TT * 64];   // H[b][t][j]  (h_t at row t)  134 MB
__device__ float g_Hp[4096 * TT * 32];   // Hp[b][t][a]                 67 MB
__device__ float g_d0[4096 * 64];        // d0[b][j]                     1 MB

// ---------------- device helpers ----------------
__device__ __forceinline__ void fma2(u64 &acc, u64 w, u64 h){
    asm("fma.rn.f32x2 %0, %1, %2, %0;" : "+l"(acc) : "l"(w), "l"(h));
}
__device__ __forceinline__ float hsum2(u64 a){
    return __uint_as_float((unsigned)a) + __uint_as_float((unsigned)(a >> 32));
}
__device__ __forceinline__ float ex2f(float x){ float y; asm("ex2.approx.f32 %0, %1;" : "=f"(y) : "f"(x)); return y; }
__device__ __forceinline__ float rcpf(float x){ float y; asm("rcp.approx.f32 %0, %1;" : "=f"(y) : "f"(x)); return y; }
__device__ __forceinline__ float sigm(float x){ return rcpf(1.0f + ex2f(-LOG2E * x)); }
__device__ __forceinline__ float tanh_acc(float x){
    float xx = fminf(15.0f, fmaxf(-15.0f, x));
    float e  = ex2f(2.0f * LOG2E * xx);
    return (e - 1.0f) * rcpf(e + 1.0f);
}
__device__ __forceinline__ float tanh_fast(float x){
    float y; asm("tanh.approx.f32 %0, %1;" : "=f"(y) : "f"(x)); return y;
}

// ================= KERNEL 1: encoder (per-b CTA, 1 barrier/step) ==============
// (verbatim from the passing R10 kernel)
#define K1_H     0                       // 129 x 64 (row 0 = h_{-1} = 0)
#define K1_HP    (K1_H + 129*64)         // 128 x 33
#define K1_XS    (K1_HP + 128*33)        // 128
#define K1_DBUF  (K1_XS + 128)           // 64
#define K1_PR    (K1_DBUF + 64)          // 128
#define K1_FLOATS (K1_PR + 128)
#define K1_BYTES  (K1_FLOATS * 4)        // 51.2 KB -> 4 CTAs/SM

extern "C" __global__ void __launch_bounds__(128, 4)
darnn_enc_pb(const float* __restrict__ x,
             const float* __restrict__ W_ih_e, const float* __restrict__ W_hh_e,
             const float* __restrict__ b_ih_e, const float* __restrict__ b_hh_e,
             const float* __restrict__ W_init, const float* __restrict__ b_init,
             const float* __restrict__ U_d)
{
    extern __shared__ __align__(16) float sm[];
    float* H    = sm + K1_H;
    float* Hp   = sm + K1_HP;
    float* xs   = sm + K1_XS;
    float* dbuf = sm + K1_DBUF;
    float* pR   = sm + K1_PR;

    const int tid  = threadIdx.x;
    const int b    = blockIdx.x;
    const int lane = tid & 31;
    const int warp = tid >> 5;
    const int jj  = warp * 16 + (lane >> 1);   // output unit 0..63
    const int kh  = lane & 1;                  // k-half

    u64 wr[16], wz[16], wn[16];
    {
        const u64* Wr = (const u64*)(W_hh_e + (jj)       * 64 + kh * 32);
        const u64* Wz = (const u64*)(W_hh_e + (64 + jj)  * 64 + kh * 32);
        const u64* Wn = (const u64*)(W_hh_e + (128 + jj) * 64 + kh * 32);
        #pragma unroll
        for (int k = 0; k < 16; k++){ wr[k] = Wr[k]; wz[k] = Wz[k]; wn[k] = Wn[k]; }
    }
    const float wih_r = W_ih_e[jj], wih_z = W_ih_e[64 + jj], wih_n = W_ih_e[128 + jj];
    const float br  = b_ih_e[jj]       + b_hh_e[jj];
    const float bz  = b_ih_e[64 + jj]  + b_hh_e[64 + jj];
    const float bin = b_ih_e[128 + jj];
    const float bhn = b_hh_e[128 + jj];

    xs[tid] = x[(size_t)b * TT + tid];
    if (tid < 64) H[tid] = 0.0f;
    __syncthreads();

    float hcur = 0.0f;
    for (int t = 0; t < TT; t++){
        const ulonglong2* hp2 = (const ulonglong2*)(H + t * 64 + kh * 32);
        u64 ar = 0ULL, az = 0ULL, an = 0ULL;
        #pragma unroll
        for (int k = 0; k < 8; k++){
            ulonglong2 h2 = hp2[k];
            fma2(ar, wr[2*k], h2.x); fma2(ar, wr[2*k+1], h2.y);
            fma2(az, wz[2*k], h2.x); fma2(az, wz[2*k+1], h2.y);
            fma2(an, wn[2*k], h2.x); fma2(an, wn[2*k+1], h2.y);
        }
        float sr = hsum2(ar); sr += __shfl_xor_sync(0xffffffffu, sr, 1);
        float sz = hsum2(az); sz += __shfl_xor_sync(0xffffffffu, sz, 1);
        float sn = hsum2(an); sn += __shfl_xor_sync(0xffffffffu, sn, 1);
        float xt = xs[t];
        float r  = sigm(fmaf(xt, wih_r, br) + sr);
        float z  = sigm(fmaf(xt, wih_z, bz) + sz);
        float n  = tanh_acc(fmaf(xt, wih_n, bin) + r * (sn + bhn));
        hcur = n + z * (hcur - n);
        H[(t + 1) * 64 + jj] = hcur;
        __syncthreads();
    }

    // ---- H_proj pass: warp owns 32 t's, lane = a
    {
        u64 ud[32];
        const u64* U = (const u64*)(U_d + lane * 64);
        #pragma unroll
        for (int k = 0; k < 32; k++) ud[k] = U[k];
        for (int tt = 0; tt < 32; tt++){
            int t = warp * 32 + tt;
            const float* hrow = H + (t + 1) * 64;
            u64 acc = 0ULL;
            #pragma unroll
            for (int k = 0; k < 16; k++){
                ulonglong2 h2 = *(const ulonglong2*)(hrow + k * 4);
                fma2(acc, ud[2*k], h2.x); fma2(acc, ud[2*k+1], h2.y);
            }
            Hp[t * 33 + lane] = hsum2(acc);
        }
    }

    // ---- d0 = W_init . h_T + b_init
    {
        const int j2  = ((warp >> 1) << 5) + lane;
        const int kh2 = warp & 1;
        const ulonglong2* Wi = (const ulonglong2*)(W_init + j2 * 64 + kh2 * 32);
        const float* hT = H + TT * 64 + kh2 * 32;
        u64 acc = 0ULL;
        #pragma unroll
        for (int k = 0; k < 8; k++){
            ulonglong2 h2 = *(const ulonglong2*)(hT + k * 4);
            ulonglong2 w2 = Wi[k];
            fma2(acc, w2.x, h2.x); fma2(acc, w2.y, h2.y);
        }
        pR[kh2 * 64 + j2] = hsum2(acc);
        __syncthreads();
        if (kh2 == 0) dbuf[j2] = pR[j2] + pR[64 + j2] + b_init[j2];
    }
    __syncthreads();

    // ---- dump to global scratch
    {
        const float4* srcH = (const float4*)(H + 64);        // rows 1..128 = h_0..h_127
        float4* dstH = (float4*)(g_H + (size_t)b * (TT * 64));
        for (int i = tid; i < TT * 64 / 4; i += 128) dstH[i] = srcH[i];
        float* dstHp = g_Hp + (size_t)b * (TT * 32);
        for (int i = tid; i < TT * 32; i += 128){
            int tt = i >> 5, a = i & 31;
            dstHp[i] = Hp[tt * 33 + a];
        }
        if (tid < 64) g_d0[(size_t)b * 64 + tid] = dbuf[tid];
    }
}

// ================= KERNEL 2: decoder (R9 skeleton + q-trick, bank-safe) =======
#define DSM_HP    0                      // 128 x 33
#define DSM_QV    (DSM_HP + 128*33)      // 128   q_t = <wout_c, h_t>
#define DSM_DBUF  (DSM_QV + 128)         // 2 x 64
#define DSM_PR    (DSM_DBUF + 128)       // 128
#define DSM_PZ    (DSM_PR + 128)         // 128
#define DSM_PN    (DSM_PZ + 128)         // 128
#define DSM_CP    (DSM_PN + 128)         // 128
#define DSM_DPV   (DSM_CP + 128)         // 32
#define DSM_VD    (DSM_DPV + 32)         // 32
#define DSM_WC    (DSM_VD + 32)          // 64
#define DSM_RED   (DSM_WC + 64)          // 16
#define DSM_FLOATS (DSM_RED + 16)
#define DSM_BYTES  (DSM_FLOATS * 4)      // ~20 KB

extern "C" __global__ void __launch_bounds__(128, 4)
darnn_decoder(const float* __restrict__ W_ih_d, const float* __restrict__ W_hh_d,
              const float* __restrict__ b_ih_d, const float* __restrict__ b_hh_d,
              const float* __restrict__ W_d,    const float* __restrict__ v_d,
              const float* __restrict__ W_out,  const float* __restrict__ b_out,
              const float* __restrict__ y0,
              float* __restrict__ out)
{
    extern __shared__ __align__(16) float sm[];
    float* Hps  = sm + DSM_HP;
    float* qv   = sm + DSM_QV;
    float* dbuf = sm + DSM_DBUF;
    float* pR   = sm + DSM_PR;
    float* pZ   = sm + DSM_PZ;
    float* pN   = sm + DSM_PN;
    float* cp   = sm + DSM_CP;
    float* dpv  = sm + DSM_DPV;
    float* vd   = sm + DSM_VD;
    float* wc   = sm + DSM_WC;
    float* red  = sm + DSM_RED;

    const int tid  = threadIdx.x;
    const int b    = blockIdx.x;
    const int lane = tid & 31;
    const int warp = tid >> 5;
    const int j    = ((warp >> 1) << 5) + lane;
    const int kh   = warp & 1;
    const bool fin = (kh == 0);

    // ---- stage Hp / d0 / wc / vd
    {
        const float* gHp = g_Hp + (size_t)b * (TT * 32);
        for (int i = tid; i < TT * 32; i += 128){
            int tt = i >> 5, a = i & 31;
            Hps[tt * 33 + a] = gHp[i];
        }
        if (tid < 64){
            dbuf[tid] = g_d0[(size_t)b * 64 + tid];
            wc[tid]   = W_out[64 + tid];
        }
        if (tid < 32) vd[tid] = v_d[tid];
    }
    __syncthreads();

    // ---- q_t = <wout_c, h_t>: thread tid = t (exact factorization of ctx)
    {
        const ulonglong2* hrow = (const ulonglong2*)(g_H + (size_t)b * (TT * 64) + tid * 64);
        const ulonglong2* wcp  = (const ulonglong2*)wc;
        u64 acc = 0ULL;
        #pragma unroll
        for (int k = 0; k < 16; k++){
            ulonglong2 h2 = hrow[k];
            ulonglong2 w2 = wcp[k];
            fma2(acc, w2.x, h2.x); fma2(acc, w2.y, h2.y);
        }
        qv[tid] = hsum2(acc);
    }

    // ---- decoder GRU weights: 3 half-rows per thread (k-split, R9 mapping)
    u64 wr[16], wz[16], wn[16];
    {
        const u64* Wr = (const u64*)(W_hh_d + (j)       * 64 + kh * 32);
        const u64* Wz = (const u64*)(W_hh_d + (64 + j)  * 64 + kh * 32);
        const u64* Wn = (const u64*)(W_hh_d + (128 + j) * 64 + kh * 32);
        #pragma unroll
        for (int k = 0; k < 16; k++){ wr[k] = Wr[k]; wz[k] = Wz[k]; wn[k] = Wn[k]; }
    }
    const float wih_r = W_ih_d[j], wih_z = W_ih_d[64 + j], wih_n = W_ih_d[128 + j];
    const float br  = b_ih_d[j]      + b_hh_d[j];
    const float bz  = b_ih_d[64 + j] + b_hh_d[64 + j];
    const float bin = b_ih_d[128 + j];
    const float bhn = b_hh_d[128 + j];
    const float wout_d = W_out[j];
    const float bo = b_out[0];
    float xdec = y0[0];
    float dj = fin ? dbuf[j] : 0.0f;
    __syncthreads();                                   // qv visible

    // ---- 24 decoder steps, 5 barriers each
    for (int s = 0; s < HORZ; s++){
        const float* drow   = dbuf + (s & 1) * 64;
        float*       drow_n = dbuf + ((s + 1) & 1) * 64;

        // GRU k-split (verbatim R9)
        {
            const float* hrow = drow + kh * 32;
            u64 ar = 0ULL, az = 0ULL, an = 0ULL;
            #pragma unroll
            for (int k = 0; k < 8; k++){
                ulonglong2 h2 = *(const ulonglong2*)(hrow + k * 4);
                fma2(ar, wr[2*k], h2.x); fma2(ar, wr[2*k+1], h2.y);
                fma2(az, wz[2*k], h2.x); fma2(az, wz[2*k+1], h2.y);
                fma2(an, wn[2*k], h2.x); fma2(an, wn[2*k+1], h2.y);
            }
            pR[kh * 64 + j] = hsum2(ar);
            pZ[kh * 64 + j] = hsum2(az);
            pN[kh * 64 + j] = hsum2(an);
        }
        __syncthreads();                               // B1
        if (fin){
            float r  = sigm(fmaf(xdec, wih_r, br) + pR[j] + pR[64 + j]);
            float z  = sigm(fmaf(xdec, wih_z, bz) + pZ[j] + pZ[64 + j]);
            float n  = tanh_acc(fmaf(xdec, wih_n, bin) + r * (pN[j] + pN[64 + j] + bhn));
            dj = n + z * (dj - n);
            drow_n[j] = dj;
            // wsum_d partial: <wout_d, d_new> over this warp's 32 j's
            float part = wout_d * dj;
            #pragma unroll
            for (int o = 16; o > 0; o >>= 1) part += __shfl_xor_sync(0xffffffffu, part, o);
            if (lane == 0) red[8 + (warp >> 1)] = part;
        }
        __syncthreads();                               // B2: d_new + wsum parts

        // d_proj quarter-split: a = lane, k-quarter = warp (W_d from GLOBAL/L1)
        {
            const ulonglong2* Wd = (const ulonglong2*)(W_d + lane * 64 + warp * 16);
            const float* dsrc = drow_n + warp * 16;
            u64 acc = 0ULL;
            #pragma unroll
            for (int k = 0; k < 4; k++){
                ulonglong2 d2 = *(const ulonglong2*)(dsrc + k * 4);
                ulonglong2 w2 = Wd[k];
                fma2(acc, w2.x, d2.x); fma2(acc, w2.y, d2.y);
            }
            cp[warp * 32 + lane] = hsum2(acc);
        }
        __syncthreads();                               // B3
        if (tid < 32) dpv[tid] = (cp[tid] + cp[32 + tid]) + (cp[64 + tid] + cp[96 + tid]);
        __syncthreads();                               // B4

        // scores: thread tid = t; softmax w/o max; Σe and Σe·q in one butterfly
        {
            const float* hpt = Hps + tid * 33;
            float sc = 0.0f;
            #pragma unroll 8
            for (int a = 0; a < 32; a++)
                sc = fmaf(vd[a], tanh_fast(dpv[a] + hpt[a]), sc);
            float e  = ex2f(sc * LOG2E);
            float eq = e * qv[tid];
            #pragma unroll
            for (int o = 16; o > 0; o >>= 1){
                e  += __shfl_xor_sync(0xffffffffu, e,  o);
                eq += __shfl_xor_sync(0xffffffffu, eq, o);
            }
            if (lane == 0){ red[warp] = e; red[4 + warp] = eq; }
        }
        __syncthreads();                               // B5

        float esum = (red[0] + red[1]) + (red[2] + red[3]);
        float eqs  = (red[4] + red[5]) + (red[6] + red[7]);
        float val  = (red[8] + red[9]) + bo + eqs * rcpf(esum);
        if (tid == 0) out[b * HORZ + s] = val;
        xdec = val;
    }
}

extern "C" void kernel_launch(void* const* d_in, const int* in_sizes, int n_in,
                              void* d_out, int out_size)
{
    (void)in_sizes; (void)n_in; (void)out_size;
    const float* x      = (const float*)d_in[0];
    const float* W_ih_e = (const float*)d_in[1];
    const float* W_hh_e = (const float*)d_in[2];
    const float* b_ih_e = (const float*)d_in[3];
    const float* b_hh_e = (const float*)d_in[4];
    // d_in[5..8] dead (encoder input attention == softmax over singleton axis)
    const float* W_init = (const float*)d_in[9];
    const float* b_init = (const float*)d_in[10];
    const float* W_ih_d = (const float*)d_in[11];
    const float* W_hh_d = (const float*)d_in[12];
    const float* b_ih_d = (const float*)d_in[13];
    const float* b_hh_d = (const float*)d_in[14];
    const float* W_d    = (const float*)d_in[15];
    const float* U_d    = (const float*)d_in[16];
    const float* v_d    = (const float*)d_in[17];
    const float* W_out  = (const float*)d_in[18];
    const float* b_out  = (const float*)d_in[19];
    const float* y0     = (const float*)d_in[20];
    float* out = (float*)d_out;

    cudaFuncSetAttribute(darnn_enc_pb,  cudaFuncAttributeMaxDynamicSharedMemorySize, K1_BYTES);
    cudaFuncSetAttribute(darnn_decoder, cudaFuncAttributeMaxDynamicSharedMemorySize, DSM_BYTES);

    darnn_enc_pb<<<4096, 128, K1_BYTES>>>(x, W_ih_e, W_hh_e, b_ih_e, b_hh_e,
                                          W_init, b_init, U_d);
    darnn_decoder<<<4096, 128, DSM_BYTES>>>(W_ih_d, W_hh_d, b_ih_d, b_hh_d,
                                            W_d, v_d, W_out, b_out, y0, out);
}

// round 12
// speedup vs baseline: 1.5339x; 1.0557x over previous
#include <cuda_runtime.h>

#define TT    128
#define HORZ  24
#define LOG2E 1.44269504f

typedef unsigned long long u64;

// ---------------- global scratch (sanctioned __device__ arrays) ----------------
__device__ float g_H [4096 * TT * 64];   // H[b][t][j]  (h_t at row t)  134 MB
__device__ float g_Hp[4096 * TT * 32];   // Hp[b][t][a]                 67 MB
__device__ float g_d0[4096 * 64];        // d0[b][j]                     1 MB

// ---------------- device helpers ----------------
__device__ __forceinline__ void fma2(u64 &acc, u64 w, u64 h){
    asm("fma.rn.f32x2 %0, %1, %2, %0;" : "+l"(acc) : "l"(w), "l"(h));
}
__device__ __forceinline__ float hsum2(u64 a){
    return __uint_as_float((unsigned)a) + __uint_as_float((unsigned)(a >> 32));
}
__device__ __forceinline__ float ex2f(float x){ float y; asm("ex2.approx.f32 %0, %1;" : "=f"(y) : "f"(x)); return y; }
__device__ __forceinline__ float rcpf(float x){ float y; asm("rcp.approx.f32 %0, %1;" : "=f"(y) : "f"(x)); return y; }
__device__ __forceinline__ float sigm(float x){ return rcpf(1.0f + ex2f(-LOG2E * x)); }
__device__ __forceinline__ float tanh_acc(float x){
    float xx = fminf(15.0f, fmaxf(-15.0f, x));
    float e  = ex2f(2.0f * LOG2E * xx);
    return (e - 1.0f) * rcpf(e + 1.0f);
}
__device__ __forceinline__ float tanh_fast(float x){
    float y; asm("tanh.approx.f32 %0, %1;" : "=f"(y) : "f"(x)); return y;
}

// ================= KERNEL 1: encoder, 2 batch elems / CTA ====================
// smem (floats): xs 2x128 | hbuf 2bufs x (2b x 64) | pR 128 | dbuf 64
#define E2_XS    0
#define E2_HB    (E2_XS + 256)
#define E2_PR    (E2_HB + 256)
#define E2_DB    (E2_PR + 128)
#define E2_FLOATS (E2_DB + 64)
#define E2_BYTES  (E2_FLOATS * 4)          // ~2.8 KB

extern "C" __global__ void __launch_bounds__(128, 4)
darnn_enc2(const float* __restrict__ x,
           const float* __restrict__ W_ih_e, const float* __restrict__ W_hh_e,
           const float* __restrict__ b_ih_e, const float* __restrict__ b_hh_e,
           const float* __restrict__ W_init, const float* __restrict__ b_init,
           const float* __restrict__ U_d)
{
    extern __shared__ __align__(16) float sm[];
    float* xs   = sm + E2_XS;
    float* hb   = sm + E2_HB;
    float* pR   = sm + E2_PR;
    float* dbuf = sm + E2_DB;

    const int tid  = threadIdx.x;
    const int lane = tid & 31;
    const int warp = tid >> 5;
    const int jj   = warp * 16 + (lane >> 1);   // output unit 0..63
    const int kh   = lane & 1;                  // k-half
    const int b0   = blockIdx.x * 2;

    // ---- encoder GRU weights: 3 half-rows (shared across both b's)
    u64 wr[16], wz[16], wn[16];
    {
        const u64* Wr = (const u64*)(W_hh_e + (jj)       * 64 + kh * 32);
        const u64* Wz = (const u64*)(W_hh_e + (64 + jj)  * 64 + kh * 32);
        const u64* Wn = (const u64*)(W_hh_e + (128 + jj) * 64 + kh * 32);
        #pragma unroll
        for (int k = 0; k < 16; k++){ wr[k] = Wr[k]; wz[k] = Wz[k]; wn[k] = Wn[k]; }
    }
    const float wih_r = W_ih_e[jj], wih_z = W_ih_e[64 + jj], wih_n = W_ih_e[128 + jj];
    const float br  = b_ih_e[jj]       + b_hh_e[jj];
    const float bz  = b_ih_e[64 + jj]  + b_hh_e[64 + jj];
    const float bin = b_ih_e[128 + jj];
    const float bhn = b_hh_e[128 + jj];

    xs[tid]       = x[(size_t)b0 * TT + tid];
    xs[128 + tid] = x[(size_t)(b0 + 1) * TT + tid];
    hb[tid] = 0.0f;                       // buf0: h_{-1} = 0 for both b's
    __syncthreads();

    // ---- 128 GRU steps, both b's interleaved, one barrier/step
    float hc0 = 0.0f, hc1 = 0.0f;
    float* gH0 = g_H + (size_t)b0 * (TT * 64) + jj;
    float* gH1 = g_H + (size_t)(b0 + 1) * (TT * 64) + jj;
    for (int t = 0; t < TT; t++){
        const int cur = (t & 1) * 128, nxt = ((t + 1) & 1) * 128;
        const ulonglong2* h0 = (const ulonglong2*)(hb + cur + kh * 32);
        const ulonglong2* h1 = (const ulonglong2*)(hb + cur + 64 + kh * 32);
        u64 ar0 = 0ULL, az0 = 0ULL, an0 = 0ULL;
        u64 ar1 = 0ULL, az1 = 0ULL, an1 = 0ULL;
        #pragma unroll
        for (int k = 0; k < 8; k++){
            ulonglong2 a = h0[k];
            ulonglong2 b = h1[k];
            fma2(ar0, wr[2*k], a.x); fma2(ar0, wr[2*k+1], a.y);
            fma2(ar1, wr[2*k], b.x); fma2(ar1, wr[2*k+1], b.y);
            fma2(az0, wz[2*k], a.x); fma2(az0, wz[2*k+1], a.y);
            fma2(az1, wz[2*k], b.x); fma2(az1, wz[2*k+1], b.y);
            fma2(an0, wn[2*k], a.x); fma2(an0, wn[2*k+1], a.y);
            fma2(an1, wn[2*k], b.x); fma2(an1, wn[2*k+1], b.y);
        }
        float sr0 = hsum2(ar0); sr0 += __shfl_xor_sync(0xffffffffu, sr0, 1);
        float sz0 = hsum2(az0); sz0 += __shfl_xor_sync(0xffffffffu, sz0, 1);
        float sn0 = hsum2(an0); sn0 += __shfl_xor_sync(0xffffffffu, sn0, 1);
        float sr1 = hsum2(ar1); sr1 += __shfl_xor_sync(0xffffffffu, sr1, 1);
        float sz1 = hsum2(az1); sz1 += __shfl_xor_sync(0xffffffffu, sz1, 1);
        float sn1 = hsum2(an1); sn1 += __shfl_xor_sync(0xffffffffu, sn1, 1);
        float xt0 = xs[t], xt1 = xs[128 + t];
        float r0 = sigm(fmaf(xt0, wih_r, br) + sr0);
        float r1 = sigm(fmaf(xt1, wih_r, br) + sr1);
        float z0 = sigm(fmaf(xt0, wih_z, bz) + sz0);
        float z1 = sigm(fmaf(xt1, wih_z, bz) + sz1);
        float n0 = tanh_acc(fmaf(xt0, wih_n, bin) + r0 * (sn0 + bhn));
        float n1 = tanh_acc(fmaf(xt1, wih_n, bin) + r1 * (sn1 + bhn));
        hc0 = n0 + z0 * (hc0 - n0);
        hc1 = n1 + z1 * (hc1 - n1);
        hb[nxt + jj]      = hc0;          // both kh lanes write same value
        hb[nxt + 64 + jj] = hc1;
        gH0[t * 64] = hc0;                // stream H to global (write-only)
        gH1[t * 64] = hc1;
        __syncthreads();
    }

    // ---- H_proj pass from g_H (L2-resident): warp owns 32 t's, lane = a
    {
        u64 ud[32];
        const u64* U = (const u64*)(U_d + lane * 64);
        #pragma unroll
        for (int k = 0; k < 32; k++) ud[k] = U[k];
        #pragma unroll
        for (int b = 0; b < 2; b++){
            const float* Hbase = g_H + (size_t)(b0 + b) * (TT * 64);
            float* Hpb = g_Hp + (size_t)(b0 + b) * (TT * 32);
            for (int tt = 0; tt < 32; tt++){
                int t = warp * 32 + tt;
                const ulonglong2* hrow = (const ulonglong2*)(Hbase + t * 64);
                u64 acc = 0ULL;
                #pragma unroll
                for (int k = 0; k < 16; k++){
                    ulonglong2 h2 = hrow[k];
                    fma2(acc, ud[2*k], h2.x); fma2(acc, ud[2*k+1], h2.y);
                }
                Hpb[t * 32 + lane] = hsum2(acc);
            }
        }
    }

    // ---- d0 = W_init . h_127 + b_init, per b (h_127 is in hbuf buf0)
    {
        const int j2  = ((warp >> 1) << 5) + lane;
        const int kh2 = warp & 1;
        const ulonglong2* Wi = (const ulonglong2*)(W_init + j2 * 64 + kh2 * 32);
        #pragma unroll
        for (int b = 0; b < 2; b++){
            const float* hT = hb + b * 64 + kh2 * 32;    // buf0 holds h_127
            u64 acc = 0ULL;
            #pragma unroll
            for (int k = 0; k < 8; k++){
                ulonglong2 h2 = *(const ulonglong2*)(hT + k * 4);
                ulonglong2 w2 = Wi[k];
                fma2(acc, w2.x, h2.x); fma2(acc, w2.y, h2.y);
            }
            pR[kh2 * 64 + j2] = hsum2(acc);
            __syncthreads();
            if (kh2 == 0) dbuf[j2] = pR[j2] + pR[64 + j2] + b_init[j2];
            __syncthreads();
            if (tid < 64) g_d0[(size_t)(b0 + b) * 64 + tid] = dbuf[tid];
            __syncthreads();
        }
    }
}

// ================= KERNEL 2: decoder (verbatim passing R11) ==================
#define DSM_HP    0                      // 128 x 33
#define DSM_QV    (DSM_HP + 128*33)      // 128   q_t = <wout_c, h_t>
#define DSM_DBUF  (DSM_QV + 128)         // 2 x 64
#define DSM_PR    (DSM_DBUF + 128)       // 128
#define DSM_PZ    (DSM_PR + 128)         // 128
#define DSM_PN    (DSM_PZ + 128)         // 128
#define DSM_CP    (DSM_PN + 128)         // 128
#define DSM_DPV   (DSM_CP + 128)         // 32
#define DSM_VD    (DSM_DPV + 32)         // 32
#define DSM_WC    (DSM_VD + 32)          // 64
#define DSM_RED   (DSM_WC + 64)          // 16
#define DSM_FLOATS (DSM_RED + 16)
#define DSM_BYTES  (DSM_FLOATS * 4)      // ~20 KB

extern "C" __global__ void __launch_bounds__(128, 4)
darnn_decoder(const float* __restrict__ W_ih_d, const float* __restrict__ W_hh_d,
              const float* __restrict__ b_ih_d, const float* __restrict__ b_hh_d,
              const float* __restrict__ W_d,    const float* __restrict__ v_d,
              const float* __restrict__ W_out,  const float* __restrict__ b_out,
              const float* __restrict__ y0,
              float* __restrict__ out)
{
    extern __shared__ __align__(16) float sm[];
    float* Hps  = sm + DSM_HP;
    float* qv   = sm + DSM_QV;
    float* dbuf = sm + DSM_DBUF;
    float* pR   = sm + DSM_PR;
    float* pZ   = sm + DSM_PZ;
    float* pN   = sm + DSM_PN;
    float* cp   = sm + DSM_CP;
    float* dpv  = sm + DSM_DPV;
    float* vd   = sm + DSM_VD;
    float* wc   = sm + DSM_WC;
    float* red  = sm + DSM_RED;

    const int tid  = threadIdx.x;
    const int b    = blockIdx.x;
    const int lane = tid & 31;
    const int warp = tid >> 5;
    const int j    = ((warp >> 1) << 5) + lane;
    const int kh   = warp & 1;
    const bool fin = (kh == 0);

    // ---- stage Hp / d0 / wc / vd
    {
        const float* gHp = g_Hp + (size_t)b * (TT * 32);
        for (int i = tid; i < TT * 32; i += 128){
            int tt = i >> 5, a = i & 31;
            Hps[tt * 33 + a] = gHp[i];
        }
        if (tid < 64){
            dbuf[tid] = g_d0[(size_t)b * 64 + tid];
            wc[tid]   = W_out[64 + tid];
        }
        if (tid < 32) vd[tid] = v_d[tid];
    }
    __syncthreads();

    // ---- q_t = <wout_c, h_t>: thread tid = t (exact factorization of ctx)
    {
        const ulonglong2* hrow = (const ulonglong2*)(g_H + (size_t)b * (TT * 64) + tid * 64);
        const ulonglong2* wcp  = (const ulonglong2*)wc;
        u64 acc = 0ULL;
        #pragma unroll
        for (int k = 0; k < 16; k++){
            ulonglong2 h2 = hrow[k];
            ulonglong2 w2 = wcp[k];
            fma2(acc, w2.x, h2.x); fma2(acc, w2.y, h2.y);
        }
        qv[tid] = hsum2(acc);
    }

    // ---- decoder GRU weights: 3 half-rows per thread (k-split)
    u64 wr[16], wz[16], wn[16];
    {
        const u64* Wr = (const u64*)(W_hh_d + (j)       * 64 + kh * 32);
        const u64* Wz = (const u64*)(W_hh_d + (64 + j)  * 64 + kh * 32);
        const u64* Wn = (const u64*)(W_hh_d + (128 + j) * 64 + kh * 32);
        #pragma unroll
        for (int k = 0; k < 16; k++){ wr[k] = Wr[k]; wz[k] = Wz[k]; wn[k] = Wn[k]; }
    }
    const float wih_r = W_ih_d[j], wih_z = W_ih_d[64 + j], wih_n = W_ih_d[128 + j];
    const float br  = b_ih_d[j]      + b_hh_d[j];
    const float bz  = b_ih_d[64 + j] + b_hh_d[64 + j];
    const float bin = b_ih_d[128 + j];
    const float bhn = b_hh_d[128 + j];
    const float wout_d = W_out[j];
    const float bo = b_out[0];
    float xdec = y0[0];
    float dj = fin ? dbuf[j] : 0.0f;
    __syncthreads();                                   // qv visible

    // ---- 24 decoder steps, 5 barriers each
    for (int s = 0; s < HORZ; s++){
        const float* drow   = dbuf + (s & 1) * 64;
        float*       drow_n = dbuf + ((s + 1) & 1) * 64;

        {
            const float* hrow = drow + kh * 32;
            u64 ar = 0ULL, az = 0ULL, an = 0ULL;
            #pragma unroll
            for (int k = 0; k < 8; k++){
                ulonglong2 h2 = *(const ulonglong2*)(hrow + k * 4);
                fma2(ar, wr[2*k], h2.x); fma2(ar, wr[2*k+1], h2.y);
                fma2(az, wz[2*k], h2.x); fma2(az, wz[2*k+1], h2.y);
                fma2(an, wn[2*k], h2.x); fma2(an, wn[2*k+1], h2.y);
            }
            pR[kh * 64 + j] = hsum2(ar);
            pZ[kh * 64 + j] = hsum2(az);
            pN[kh * 64 + j] = hsum2(an);
        }
        __syncthreads();                               // B1
        if (fin){
            float r  = sigm(fmaf(xdec, wih_r, br) + pR[j] + pR[64 + j]);
            float z  = sigm(fmaf(xdec, wih_z, bz) + pZ[j] + pZ[64 + j]);
            float n  = tanh_acc(fmaf(xdec, wih_n, bin) + r * (pN[j] + pN[64 + j] + bhn));
            dj = n + z * (dj - n);
            drow_n[j] = dj;
            float part = wout_d * dj;
            #pragma unroll
            for (int o = 16; o > 0; o >>= 1) part += __shfl_xor_sync(0xffffffffu, part, o);
            if (lane == 0) red[8 + (warp >> 1)] = part;
        }
        __syncthreads();                               // B2: d_new + wsum parts

        // d_proj quarter-split: a = lane, k-quarter = warp (W_d from GLOBAL/L1)
        {
            const ulonglong2* Wd = (const ulonglong2*)(W_d + lane * 64 + warp * 16);
            const float* dsrc = drow_n + warp * 16;
            u64 acc = 0ULL;
            #pragma unroll
            for (int k = 0; k < 4; k++){
                ulonglong2 d2 = *(const ulonglong2*)(dsrc + k * 4);
                ulonglong2 w2 = Wd[k];
                fma2(acc, w2.x, d2.x); fma2(acc, w2.y, d2.y);
            }
            cp[warp * 32 + lane] = hsum2(acc);
        }
        __syncthreads();                               // B3
        if (tid < 32) dpv[tid] = (cp[tid] + cp[32 + tid]) + (cp[64 + tid] + cp[96 + tid]);
        __syncthreads();                               // B4

        // scores: thread tid = t; softmax w/o max; Σe and Σe·q in one butterfly
        {
            const float* hpt = Hps + tid * 33;
            float sc = 0.0f;
            #pragma unroll 8
            for (int a = 0; a < 32; a++)
                sc = fmaf(vd[a], tanh_fast(dpv[a] + hpt[a]), sc);
            float e  = ex2f(sc * LOG2E);
            float eq = e * qv[tid];
            #pragma unroll
            for (int o = 16; o > 0; o >>= 1){
                e  += __shfl_xor_sync(0xffffffffu, e,  o);
                eq += __shfl_xor_sync(0xffffffffu, eq, o);
            }
            if (lane == 0){ red[warp] = e; red[4 + warp] = eq; }
        }
        __syncthreads();                               // B5

        float esum = (red[0] + red[1]) + (red[2] + red[3]);
        float eqs  = (red[4] + red[5]) + (red[6] + red[7]);
        float val  = (red[8] + red[9]) + bo + eqs * rcpf(esum);
        if (tid == 0) out[b * HORZ + s] = val;
        xdec = val;
    }
}

extern "C" void kernel_launch(void* const* d_in, const int* in_sizes, int n_in,
                              void* d_out, int out_size)
{
    (void)in_sizes; (void)n_in; (void)out_size;
    const float* x      = (const float*)d_in[0];
    const float* W_ih_e = (const float*)d_in[1];
    const float* W_hh_e = (const float*)d_in[2];
    const float* b_ih_e = (const float*)d_in[3];
    const float* b_hh_e = (const float*)d_in[4];
    // d_in[5..8] dead (encoder input attention == softmax over singleton axis)
    const float* W_init = (const float*)d_in[9];
    const float* b_init = (const float*)d_in[10];
    const float* W_ih_d = (const float*)d_in[11];
    const float* W_hh_d = (const float*)d_in[12];
    const float* b_ih_d = (const float*)d_in[13];
    const float* b_hh_d = (const float*)d_in[14];
    const float* W_d    = (const float*)d_in[15];
    const float* U_d    = (const float*)d_in[16];
    const float* v_d    = (const float*)d_in[17];
    const float* W_out  = (const float*)d_in[18];
    const float* b_out  = (const float*)d_in[19];
    const float* y0     = (const float*)d_in[20];
    float* out = (float*)d_out;

    cudaFuncSetAttribute(darnn_enc2,    cudaFuncAttributeMaxDynamicSharedMemorySize, E2_BYTES);
    cudaFuncSetAttribute(darnn_decoder, cudaFuncAttributeMaxDynamicSharedMemorySize, DSM_BYTES);

    darnn_enc2<<<2048, 128, E2_BYTES>>>(x, W_ih_e, W_hh_e, b_ih_e, b_hh_e,
                                        W_init, b_init, U_d);
    darnn_decoder<<<4096, 128, DSM_BYTES>>>(W_ih_d, W_hh_d, b_ih_d, b_hh_d,
                                            W_d, v_d, W_out, b_out, y0, out);
}

// round 13
// speedup vs baseline: 1.5432x; 1.0061x over previous
#include <cuda_runtime.h>

#define TT    128
#define HORZ  24
#define LOG2E 1.44269504f

typedef unsigned long long u64;

// ---------------- global scratch (sanctioned __device__ arrays) ----------------
__device__ float g_H [4096 * TT * 64];   // H[b][t][j]  (h_t at row t)  134 MB
__device__ float g_Hp[4096 * TT * 32];   // Hp[b][t][a]                 67 MB
__device__ float g_d0[4096 * 64];        // d0[b][j]                     1 MB

// ---------------- device helpers ----------------
__device__ __forceinline__ void fma2(u64 &acc, u64 w, u64 h){
    asm("fma.rn.f32x2 %0, %1, %2, %0;" : "+l"(acc) : "l"(w), "l"(h));
}
__device__ __forceinline__ float hsum2(u64 a){
    return __uint_as_float((unsigned)a) + __uint_as_float((unsigned)(a >> 32));
}
__device__ __forceinline__ float ex2f(float x){ float y; asm("ex2.approx.f32 %0, %1;" : "=f"(y) : "f"(x)); return y; }
__device__ __forceinline__ float rcpf(float x){ float y; asm("rcp.approx.f32 %0, %1;" : "=f"(y) : "f"(x)); return y; }
__device__ __forceinline__ float sigm(float x){ return rcpf(1.0f + ex2f(-LOG2E * x)); }
__device__ __forceinline__ float tanh_acc(float x){
    float xx = fminf(15.0f, fmaxf(-15.0f, x));
    float e  = ex2f(2.0f * LOG2E * xx);
    return (e - 1.0f) * rcpf(e + 1.0f);
}
__device__ __forceinline__ float tanh_fast(float x){
    float y; asm("tanh.approx.f32 %0, %1;" : "=f"(y) : "f"(x)); return y;
}

// ================= KERNEL 1: encoder, 2 batch elems / CTA (verbatim R12) =====
#define E2_XS    0
#define E2_HB    (E2_XS + 256)
#define E2_PR    (E2_HB + 256)
#define E2_DB    (E2_PR + 128)
#define E2_FLOATS (E2_DB + 64)
#define E2_BYTES  (E2_FLOATS * 4)          // ~2.8 KB

extern "C" __global__ void __launch_bounds__(128, 4)
darnn_enc2(const float* __restrict__ x,
           const float* __restrict__ W_ih_e, const float* __restrict__ W_hh_e,
           const float* __restrict__ b_ih_e, const float* __restrict__ b_hh_e,
           const float* __restrict__ W_init, const float* __restrict__ b_init,
           const float* __restrict__ U_d)
{
    extern __shared__ __align__(16) float sm[];
    float* xs   = sm + E2_XS;
    float* hb   = sm + E2_HB;
    float* pR   = sm + E2_PR;
    float* dbuf = sm + E2_DB;

    const int tid  = threadIdx.x;
    const int lane = tid & 31;
    const int warp = tid >> 5;
    const int jj   = warp * 16 + (lane >> 1);   // output unit 0..63
    const int kh   = lane & 1;                  // k-half
    const int b0   = blockIdx.x * 2;

    u64 wr[16], wz[16], wn[16];
    {
        const u64* Wr = (const u64*)(W_hh_e + (jj)       * 64 + kh * 32);
        const u64* Wz = (const u64*)(W_hh_e + (64 + jj)  * 64 + kh * 32);
        const u64* Wn = (const u64*)(W_hh_e + (128 + jj) * 64 + kh * 32);
        #pragma unroll
        for (int k = 0; k < 16; k++){ wr[k] = Wr[k]; wz[k] = Wz[k]; wn[k] = Wn[k]; }
    }
    const float wih_r = W_ih_e[jj], wih_z = W_ih_e[64 + jj], wih_n = W_ih_e[128 + jj];
    const float br  = b_ih_e[jj]       + b_hh_e[jj];
    const float bz  = b_ih_e[64 + jj]  + b_hh_e[64 + jj];
    const float bin = b_ih_e[128 + jj];
    const float bhn = b_hh_e[128 + jj];

    xs[tid]       = x[(size_t)b0 * TT + tid];
    xs[128 + tid] = x[(size_t)(b0 + 1) * TT + tid];
    hb[tid] = 0.0f;
    __syncthreads();

    float hc0 = 0.0f, hc1 = 0.0f;
    float* gH0 = g_H + (size_t)b0 * (TT * 64) + jj;
    float* gH1 = g_H + (size_t)(b0 + 1) * (TT * 64) + jj;
    for (int t = 0; t < TT; t++){
        const int cur = (t & 1) * 128, nxt = ((t + 1) & 1) * 128;
        const ulonglong2* h0 = (const ulonglong2*)(hb + cur + kh * 32);
        const ulonglong2* h1 = (const ulonglong2*)(hb + cur + 64 + kh * 32);
        u64 ar0 = 0ULL, az0 = 0ULL, an0 = 0ULL;
        u64 ar1 = 0ULL, az1 = 0ULL, an1 = 0ULL;
        #pragma unroll
        for (int k = 0; k < 8; k++){
            ulonglong2 a = h0[k];
            ulonglong2 b = h1[k];
            fma2(ar0, wr[2*k], a.x); fma2(ar0, wr[2*k+1], a.y);
            fma2(ar1, wr[2*k], b.x); fma2(ar1, wr[2*k+1], b.y);
            fma2(az0, wz[2*k], a.x); fma2(az0, wz[2*k+1], a.y);
            fma2(az1, wz[2*k], b.x); fma2(az1, wz[2*k+1], b.y);
            fma2(an0, wn[2*k], a.x); fma2(an0, wn[2*k+1], a.y);
            fma2(an1, wn[2*k], b.x); fma2(an1, wn[2*k+1], b.y);
        }
        float sr0 = hsum2(ar0); sr0 += __shfl_xor_sync(0xffffffffu, sr0, 1);
        float sz0 = hsum2(az0); sz0 += __shfl_xor_sync(0xffffffffu, sz0, 1);
        float sn0 = hsum2(an0); sn0 += __shfl_xor_sync(0xffffffffu, sn0, 1);
        float sr1 = hsum2(ar1); sr1 += __shfl_xor_sync(0xffffffffu, sr1, 1);
        float sz1 = hsum2(az1); sz1 += __shfl_xor_sync(0xffffffffu, sz1, 1);
        float sn1 = hsum2(an1); sn1 += __shfl_xor_sync(0xffffffffu, sn1, 1);
        float xt0 = xs[t], xt1 = xs[128 + t];
        float r0 = sigm(fmaf(xt0, wih_r, br) + sr0);
        float r1 = sigm(fmaf(xt1, wih_r, br) + sr1);
        float z0 = sigm(fmaf(xt0, wih_z, bz) + sz0);
        float z1 = sigm(fmaf(xt1, wih_z, bz) + sz1);
        float n0 = tanh_acc(fmaf(xt0, wih_n, bin) + r0 * (sn0 + bhn));
        float n1 = tanh_acc(fmaf(xt1, wih_n, bin) + r1 * (sn1 + bhn));
        hc0 = n0 + z0 * (hc0 - n0);
        hc1 = n1 + z1 * (hc1 - n1);
        hb[nxt + jj]      = hc0;
        hb[nxt + 64 + jj] = hc1;
        gH0[t * 64] = hc0;
        gH1[t * 64] = hc1;
        __syncthreads();
    }

    // ---- H_proj pass from g_H (L2-resident): warp owns 32 t's, lane = a
    {
        u64 ud[32];
        const u64* U = (const u64*)(U_d + lane * 64);
        #pragma unroll
        for (int k = 0; k < 32; k++) ud[k] = U[k];
        #pragma unroll
        for (int b = 0; b < 2; b++){
            const float* Hbase = g_H + (size_t)(b0 + b) * (TT * 64);
            float* Hpb = g_Hp + (size_t)(b0 + b) * (TT * 32);
            for (int tt = 0; tt < 32; tt++){
                int t = warp * 32 + tt;
                const ulonglong2* hrow = (const ulonglong2*)(Hbase + t * 64);
                u64 acc = 0ULL;
                #pragma unroll
                for (int k = 0; k < 16; k++){
                    ulonglong2 h2 = hrow[k];
                    fma2(acc, ud[2*k], h2.x); fma2(acc, ud[2*k+1], h2.y);
                }
                Hpb[t * 32 + lane] = hsum2(acc);
            }
        }
    }

    // ---- d0 = W_init . h_127 + b_init, per b (h_127 is in hbuf buf0)
    {
        const int j2  = ((warp >> 1) << 5) + lane;
        const int kh2 = warp & 1;
        const ulonglong2* Wi = (const ulonglong2*)(W_init + j2 * 64 + kh2 * 32);
        #pragma unroll
        for (int b = 0; b < 2; b++){
            const float* hT = hb + b * 64 + kh2 * 32;
            u64 acc = 0ULL;
            #pragma unroll
            for (int k = 0; k < 8; k++){
                ulonglong2 h2 = *(const ulonglong2*)(hT + k * 4);
                ulonglong2 w2 = Wi[k];
                fma2(acc, w2.x, h2.x); fma2(acc, w2.y, h2.y);
            }
            pR[kh2 * 64 + j2] = hsum2(acc);
            __syncthreads();
            if (kh2 == 0) dbuf[j2] = pR[j2] + pR[64 + j2] + b_init[j2];
            __syncthreads();
            if (tid < 64) g_d0[(size_t)(b0 + b) * 64 + tid] = dbuf[tid];
            __syncthreads();
        }
    }
}

// ================= KERNEL 2: decoder (4 bars/step, vectorized score LDS) =====
#define DSM_HP    0                      // 128 x 34 (8B-aligned rows)
#define DSM_QV    (DSM_HP + 128*34)      // 128
#define DSM_DBUF  (DSM_QV + 128)         // 2 x 64
#define DSM_CP    (DSM_DBUF + 128)       // 128
#define DSM_DPV   (DSM_CP + 128)         // 32
#define DSM_VD    (DSM_DPV + 32)         // 32
#define DSM_WC    (DSM_VD + 32)          // 64
#define DSM_RED   (DSM_WC + 64)          // 16
#define DSM_FLOATS (DSM_RED + 16)
#define DSM_BYTES  (DSM_FLOATS * 4)      // ~19.6 KB

extern "C" __global__ void __launch_bounds__(128, 4)
darnn_decoder(const float* __restrict__ W_ih_d, const float* __restrict__ W_hh_d,
              const float* __restrict__ b_ih_d, const float* __restrict__ b_hh_d,
              const float* __restrict__ W_d,    const float* __restrict__ v_d,
              const float* __restrict__ W_out,  const float* __restrict__ b_out,
              const float* __restrict__ y0,
              float* __restrict__ out)
{
    extern __shared__ __align__(16) float sm[];
    float* Hps  = sm + DSM_HP;
    float* qv   = sm + DSM_QV;
    float* dbuf = sm + DSM_DBUF;
    float* cp   = sm + DSM_CP;
    float* dpv  = sm + DSM_DPV;
    float* vd   = sm + DSM_VD;
    float* wc   = sm + DSM_WC;
    float* red  = sm + DSM_RED;

    const int tid  = threadIdx.x;
    const int b    = blockIdx.x;
    const int lane = tid & 31;
    const int warp = tid >> 5;
    const int jj   = warp * 16 + (lane >> 1);   // GRU output unit (pair-split)
    const int kh   = lane & 1;                  // k-half

    // ---- stage Hp (stride 34) / d0 / wc / vd
    {
        const float* gHp = g_Hp + (size_t)b * (TT * 32);
        for (int i = tid; i < TT * 32; i += 128){
            int tt = i >> 5, a = i & 31;
            Hps[tt * 34 + a] = gHp[i];
        }
        if (tid < 64){
            dbuf[tid] = g_d0[(size_t)b * 64 + tid];
            wc[tid]   = W_out[64 + tid];
        }
        if (tid < 32) vd[tid] = v_d[tid];
    }
    __syncthreads();

    // ---- q_t = <wout_c, h_t>: thread tid = t (exact factorization of ctx)
    {
        const ulonglong2* hrow = (const ulonglong2*)(g_H + (size_t)b * (TT * 64) + tid * 64);
        const ulonglong2* wcp  = (const ulonglong2*)wc;
        u64 acc = 0ULL;
        #pragma unroll
        for (int k = 0; k < 16; k++){
            ulonglong2 h2 = hrow[k];
            ulonglong2 w2 = wcp[k];
            fma2(acc, w2.x, h2.x); fma2(acc, w2.y, h2.y);
        }
        qv[tid] = hsum2(acc);
    }

    // ---- decoder GRU weights: 3 half-rows (pair-split mapping)
    u64 wr[16], wz[16], wn[16];
    {
        const u64* Wr = (const u64*)(W_hh_d + (jj)       * 64 + kh * 32);
        const u64* Wz = (const u64*)(W_hh_d + (64 + jj)  * 64 + kh * 32);
        const u64* Wn = (const u64*)(W_hh_d + (128 + jj) * 64 + kh * 32);
        #pragma unroll
        for (int k = 0; k < 16; k++){ wr[k] = Wr[k]; wz[k] = Wz[k]; wn[k] = Wn[k]; }
    }
    const float wih_r = W_ih_d[jj], wih_z = W_ih_d[64 + jj], wih_n = W_ih_d[128 + jj];
    const float br  = b_ih_d[jj]      + b_hh_d[jj];
    const float bz  = b_ih_d[64 + jj] + b_hh_d[64 + jj];
    const float bin = b_ih_d[128 + jj];
    const float bhn = b_hh_d[128 + jj];
    const float wout_d = W_out[jj];
    const float bo = b_out[0];
    float xdec = y0[0];
    __syncthreads();                                   // qv + dbuf visible
    float dj = dbuf[jj];                               // all threads (pair dup)

    // ---- 24 decoder steps, 4 barriers each
    for (int s = 0; s < HORZ; s++){
        const float* drow   = dbuf + (s & 1) * 64;
        float*       drow_n = dbuf + ((s + 1) & 1) * 64;

        // GRU pair-split: k-half per adjacent lane, shfl combine, dup finalize
        {
            const ulonglong2* dp2 = (const ulonglong2*)(drow + kh * 32);
            u64 ar = 0ULL, az = 0ULL, an = 0ULL;
            #pragma unroll
            for (int k = 0; k < 8; k++){
                ulonglong2 h2 = dp2[k];
                fma2(ar, wr[2*k], h2.x); fma2(ar, wr[2*k+1], h2.y);
                fma2(az, wz[2*k], h2.x); fma2(az, wz[2*k+1], h2.y);
                fma2(an, wn[2*k], h2.x); fma2(an, wn[2*k+1], h2.y);
            }
            float sr = hsum2(ar); sr += __shfl_xor_sync(0xffffffffu, sr, 1);
            float sz = hsum2(az); sz += __shfl_xor_sync(0xffffffffu, sz, 1);
            float sn = hsum2(an); sn += __shfl_xor_sync(0xffffffffu, sn, 1);
            float r  = sigm(fmaf(xdec, wih_r, br) + sr);
            float z  = sigm(fmaf(xdec, wih_z, bz) + sz);
            float n  = tanh_acc(fmaf(xdec, wih_n, bin) + r * (sn + bhn));
            dj = n + z * (dj - n);
            drow_n[jj] = dj;                           // pair lanes write same value
            // wsum partial: each j appears twice in the warp -> halve at the end
            float part = wout_d * dj;
            #pragma unroll
            for (int o = 16; o > 0; o >>= 1) part += __shfl_xor_sync(0xffffffffu, part, o);
            if (lane == 0) red[8 + warp] = part;
        }
        __syncthreads();                               // B1: d_new + wsum parts

        // d_proj quarter-split: a = lane, k-quarter = warp (W_d from GLOBAL/L1)
        {
            const ulonglong2* Wd = (const ulonglong2*)(W_d + lane * 64 + warp * 16);
            const float* dsrc = drow_n + warp * 16;
            u64 acc = 0ULL;
            #pragma unroll
            for (int k = 0; k < 4; k++){
                ulonglong2 d2 = *(const ulonglong2*)(dsrc + k * 4);
                ulonglong2 w2 = Wd[k];
                fma2(acc, w2.x, d2.x); fma2(acc, w2.y, d2.y);
            }
            cp[warp * 32 + lane] = hsum2(acc);
        }
        __syncthreads();                               // B2
        if (tid < 32) dpv[tid] = (cp[tid] + cp[32 + tid]) + (cp[64 + tid] + cp[96 + tid]);
        __syncthreads();                               // B3

        // scores: thread tid = t; float2 LDS (half the load instructions)
        {
            const float2* hp2 = (const float2*)(Hps + tid * 34);
            float sc = 0.0f;
            #pragma unroll
            for (int k = 0; k < 16; k++){
                float2 h  = hp2[k];
                float2 dp = *(const float2*)(dpv + 2 * k);   // broadcast
                float2 vv = *(const float2*)(vd  + 2 * k);   // broadcast
                sc = fmaf(vv.x, tanh_fast(dp.x + h.x), sc);
                sc = fmaf(vv.y, tanh_fast(dp.y + h.y), sc);
            }
            float e  = ex2f(sc * LOG2E);               // softmax w/o max (bounded)
            float eq = e * qv[tid];
            #pragma unroll
            for (int o = 16; o > 0; o >>= 1){
                e  += __shfl_xor_sync(0xffffffffu, e,  o);
                eq += __shfl_xor_sync(0xffffffffu, eq, o);
            }
            if (lane == 0){ red[warp] = e; red[4 + warp] = eq; }
        }
        __syncthreads();                               // B4

        float esum = (red[0] + red[1]) + (red[2] + red[3]);
        float eqs  = (red[4] + red[5]) + (red[6] + red[7]);
        float wsum = ((red[8] + red[9]) + (red[10] + red[11])) * 0.5f;
        float val  = wsum + bo + eqs * rcpf(esum);
        if (tid == 0) out[b * HORZ + s] = val;
        xdec = val;
    }
}

extern "C" void kernel_launch(void* const* d_in, const int* in_sizes, int n_in,
                              void* d_out, int out_size)
{
    (void)in_sizes; (void)n_in; (void)out_size;
    const float* x      = (const float*)d_in[0];
    const float* W_ih_e = (const float*)d_in[1];
    const float* W_hh_e = (const float*)d_in[2];
    const float* b_ih_e = (const float*)d_in[3];
    const float* b_hh_e = (const float*)d_in[4];
    // d_in[5..8] dead (encoder input attention == softmax over singleton axis)
    const float* W_init = (const float*)d_in[9];
    const float* b_init = (const float*)d_in[10];
    const float* W_ih_d = (const float*)d_in[11];
    const float* W_hh_d = (const float*)d_in[12];
    const float* b_ih_d = (const float*)d_in[13];
    const float* b_hh_d = (const float*)d_in[14];
    const float* W_d    = (const float*)d_in[15];
    const float* U_d    = (const float*)d_in[16];
    const float* v_d    = (const float*)d_in[17];
    const float* W_out  = (const float*)d_in[18];
    const float* b_out  = (const float*)d_in[19];
    const float* y0     = (const float*)d_in[20];
    float* out = (float*)d_out;

    cudaFuncSetAttribute(darnn_enc2,    cudaFuncAttributeMaxDynamicSharedMemorySize, E2_BYTES);
    cudaFuncSetAttribute(darnn_decoder, cudaFuncAttributeMaxDynamicSharedMemorySize, DSM_BYTES);

    darnn_enc2<<<2048, 128, E2_BYTES>>>(x, W_ih_e, W_hh_e, b_ih_e, b_hh_e,
                                        W_init, b_init, U_d);
    darnn_decoder<<<4096, 128, DSM_BYTES>>>(W_ih_d, W_hh_d, b_ih_d, b_hh_d,
                                            W_d, v_d, W_out, b_out, y0, out);
}

// round 16
// speedup vs baseline: 1.7372x; 1.1257x over previous
#include <cuda_runtime.h>

#define TT    128
#define HORZ  24
#define LOG2E 1.44269504f

typedef unsigned long long u64;

// ---------------- global scratch (sanctioned __device__ arrays) ----------------
__device__ float g_H [4096 * TT * 64];   // H[b][t][j]  (h_t at row t)  134 MB
__device__ float g_Hp[4096 * TT * 32];   // Hp[b][t][a]                 67 MB
__device__ float g_d0[4096 * 64];        // d0[b][j]                     1 MB

// ---------------- device helpers ----------------
__device__ __forceinline__ void fma2(u64 &acc, u64 w, u64 h){
    asm("fma.rn.f32x2 %0, %1, %2, %0;" : "+l"(acc) : "l"(w), "l"(h));
}
__device__ __forceinline__ float hsum2(u64 a){
    return __uint_as_float((unsigned)a) + __uint_as_float((unsigned)(a >> 32));
}
__device__ __forceinline__ float ex2f(float x){ float y; asm("ex2.approx.f32 %0, %1;" : "=f"(y) : "f"(x)); return y; }
__device__ __forceinline__ float rcpf(float x){ float y; asm("rcp.approx.f32 %0, %1;" : "=f"(y) : "f"(x)); return y; }
__device__ __forceinline__ float sigm(float x){ return rcpf(1.0f + ex2f(-LOG2E * x)); }
__device__ __forceinline__ float tanh_acc(float x){
    float xx = fminf(15.0f, fmaxf(-15.0f, x));
    float e  = ex2f(2.0f * LOG2E * xx);
    return (e - 1.0f) * rcpf(e + 1.0f);
}
__device__ __forceinline__ float tanh_fast(float x){
    float y; asm("tanh.approx.f32 %0, %1;" : "=f"(y) : "f"(x)); return y;
}

// ================= KERNEL 1: encoder, 2 batch elems / CTA (verbatim R12) =====
#define E2_XS    0
#define E2_HB    (E2_XS + 256)
#define E2_PR    (E2_HB + 256)
#define E2_DB    (E2_PR + 128)
#define E2_FLOATS (E2_DB + 64)
#define E2_BYTES  (E2_FLOATS * 4)          // ~2.8 KB

extern "C" __global__ void __launch_bounds__(128, 4)
darnn_enc2(const float* __restrict__ x,
           const float* __restrict__ W_ih_e, const float* __restrict__ W_hh_e,
           const float* __restrict__ b_ih_e, const float* __restrict__ b_hh_e,
           const float* __restrict__ W_init, const float* __restrict__ b_init,
           const float* __restrict__ U_d)
{
    extern __shared__ __align__(16) float sm[];
    float* xs   = sm + E2_XS;
    float* hb   = sm + E2_HB;
    float* pR   = sm + E2_PR;
    float* dbuf = sm + E2_DB;

    const int tid  = threadIdx.x;
    const int lane = tid & 31;
    const int warp = tid >> 5;
    const int jj   = warp * 16 + (lane >> 1);
    const int kh   = lane & 1;
    const int b0   = blockIdx.x * 2;

    u64 wr[16], wz[16], wn[16];
    {
        const u64* Wr = (const u64*)(W_hh_e + (jj)       * 64 + kh * 32);
        const u64* Wz = (const u64*)(W_hh_e + (64 + jj)  * 64 + kh * 32);
        const u64* Wn = (const u64*)(W_hh_e + (128 + jj) * 64 + kh * 32);
        #pragma unroll
        for (int k = 0; k < 16; k++){ wr[k] = Wr[k]; wz[k] = Wz[k]; wn[k] = Wn[k]; }
    }
    const float wih_r = W_ih_e[jj], wih_z = W_ih_e[64 + jj], wih_n = W_ih_e[128 + jj];
    const float br  = b_ih_e[jj]       + b_hh_e[jj];
    const float bz  = b_ih_e[64 + jj]  + b_hh_e[64 + jj];
    const float bin = b_ih_e[128 + jj];
    const float bhn = b_hh_e[128 + jj];

    xs[tid]       = x[(size_t)b0 * TT + tid];
    xs[128 + tid] = x[(size_t)(b0 + 1) * TT + tid];
    hb[tid] = 0.0f;
    __syncthreads();

    float hc0 = 0.0f, hc1 = 0.0f;
    float* gH0 = g_H + (size_t)b0 * (TT * 64) + jj;
    float* gH1 = g_H + (size_t)(b0 + 1) * (TT * 64) + jj;
    for (int t = 0; t < TT; t++){
        const int cur = (t & 1) * 128, nxt = ((t + 1) & 1) * 128;
        const ulonglong2* h0 = (const ulonglong2*)(hb + cur + kh * 32);
        const ulonglong2* h1 = (const ulonglong2*)(hb + cur + 64 + kh * 32);
        u64 ar0 = 0ULL, az0 = 0ULL, an0 = 0ULL;
        u64 ar1 = 0ULL, az1 = 0ULL, an1 = 0ULL;
        #pragma unroll
        for (int k = 0; k < 8; k++){
            ulonglong2 a = h0[k];
            ulonglong2 b = h1[k];
            fma2(ar0, wr[2*k], a.x); fma2(ar0, wr[2*k+1], a.y);
            fma2(ar1, wr[2*k], b.x); fma2(ar1, wr[2*k+1], b.y);
            fma2(az0, wz[2*k], a.x); fma2(az0, wz[2*k+1], a.y);
            fma2(az1, wz[2*k], b.x); fma2(az1, wz[2*k+1], b.y);
            fma2(an0, wn[2*k], a.x); fma2(an0, wn[2*k+1], a.y);
            fma2(an1, wn[2*k], b.x); fma2(an1, wn[2*k+1], b.y);
        }
        float sr0 = hsum2(ar0); sr0 += __shfl_xor_sync(0xffffffffu, sr0, 1);
        float sz0 = hsum2(az0); sz0 += __shfl_xor_sync(0xffffffffu, sz0, 1);
        float sn0 = hsum2(an0); sn0 += __shfl_xor_sync(0xffffffffu, sn0, 1);
        float sr1 = hsum2(ar1); sr1 += __shfl_xor_sync(0xffffffffu, sr1, 1);
        float sz1 = hsum2(az1); sz1 += __shfl_xor_sync(0xffffffffu, sz1, 1);
        float sn1 = hsum2(an1); sn1 += __shfl_xor_sync(0xffffffffu, sn1, 1);
        float xt0 = xs[t], xt1 = xs[128 + t];
        float r0 = sigm(fmaf(xt0, wih_r, br) + sr0);
        float r1 = sigm(fmaf(xt1, wih_r, br) + sr1);
        float z0 = sigm(fmaf(xt0, wih_z, bz) + sz0);
        float z1 = sigm(fmaf(xt1, wih_z, bz) + sz1);
        float n0 = tanh_acc(fmaf(xt0, wih_n, bin) + r0 * (sn0 + bhn));
        float n1 = tanh_acc(fmaf(xt1, wih_n, bin) + r1 * (sn1 + bhn));
        hc0 = n0 + z0 * (hc0 - n0);
        hc1 = n1 + z1 * (hc1 - n1);
        hb[nxt + jj]      = hc0;
        hb[nxt + 64 + jj] = hc1;
        gH0[t * 64] = hc0;
        gH1[t * 64] = hc1;
        __syncthreads();
    }

    // ---- H_proj pass from g_H (L2-resident): warp owns 32 t's, lane = a
    {
        u64 ud[32];
        const u64* U = (const u64*)(U_d + lane * 64);
        #pragma unroll
        for (int k = 0; k < 32; k++) ud[k] = U[k];
        #pragma unroll
        for (int b = 0; b < 2; b++){
            const float* Hbase = g_H + (size_t)(b0 + b) * (TT * 64);
            float* Hpb = g_Hp + (size_t)(b0 + b) * (TT * 32);
            for (int tt = 0; tt < 32; tt++){
                int t = warp * 32 + tt;
                const ulonglong2* hrow = (const ulonglong2*)(Hbase + t * 64);
                u64 acc = 0ULL;
                #pragma unroll
                for (int k = 0; k < 16; k++){
                    ulonglong2 h2 = hrow[k];
                    fma2(acc, ud[2*k], h2.x); fma2(acc, ud[2*k+1], h2.y);
                }
                Hpb[t * 32 + lane] = hsum2(acc);
            }
        }
    }

    // ---- d0 = W_init . h_127 + b_init, per b (h_127 is in hbuf buf0)
    {
        const int j2  = ((warp >> 1) << 5) + lane;
        const int kh2 = warp & 1;
        const ulonglong2* Wi = (const ulonglong2*)(W_init + j2 * 64 + kh2 * 32);
        #pragma unroll
        for (int b = 0; b < 2; b++){
            const float* hT = hb + b * 64 + kh2 * 32;
            u64 acc = 0ULL;
            #pragma unroll
            for (int k = 0; k < 8; k++){
                ulonglong2 h2 = *(const ulonglong2*)(hT + k * 4);
                ulonglong2 w2 = Wi[k];
                fma2(acc, w2.x, h2.x); fma2(acc, w2.y, h2.y);
            }
            pR[kh2 * 64 + j2] = hsum2(acc);
            __syncthreads();
            if (kh2 == 0) dbuf[j2] = pR[j2] + pR[64 + j2] + b_init[j2];
            __syncthreads();
            if (tid < 64) g_d0[(size_t)(b0 + b) * 64 + tid] = dbuf[tid];
            __syncthreads();
        }
    }
}

// ================= KERNEL 2: decoder, 2 batch elems / CTA (R13 logic x2) =====
#define DSM_HP    0                       // 2 x 128 x 34
#define DSM_QV    (DSM_HP + 2*128*34)     // 2 x 128
#define DSM_DBUF  (DSM_QV + 256)          // 2 bufs x 2 b x 64
#define DSM_CP    (DSM_DBUF + 256)        // 2 x 128
#define DSM_DPV   (DSM_CP + 256)          // 2 x 32
#define DSM_VD    (DSM_DPV + 64)          // 32
#define DSM_WC    (DSM_VD + 32)           // 64
#define DSM_RED   (DSM_WC + 64)           // 32
#define DSM_FLOATS (DSM_RED + 32)
#define DSM_BYTES  (DSM_FLOATS * 4)       // ~38.7 KB -> 4 CTAs/SM

extern "C" __global__ void __launch_bounds__(128, 4)
darnn_dec2(const float* __restrict__ W_ih_d, const float* __restrict__ W_hh_d,
           const float* __restrict__ b_ih_d, const float* __restrict__ b_hh_d,
           const float* __restrict__ W_d,    const float* __restrict__ v_d,
           const float* __restrict__ W_out,  const float* __restrict__ b_out,
           const float* __restrict__ y0,
           float* __restrict__ out)
{
    extern __shared__ __align__(16) float sm[];
    float* Hps  = sm + DSM_HP;            // Hps + bsel*128*34
    float* qv   = sm + DSM_QV;            // qv  + bsel*128
    float* dbuf = sm + DSM_DBUF;          // [buf][b][j]
    float* cp   = sm + DSM_CP;            // cp  + bsel*128
    float* dpv  = sm + DSM_DPV;           // dpv + bsel*32
    float* vd   = sm + DSM_VD;
    float* wc   = sm + DSM_WC;
    float* red  = sm + DSM_RED;

    const int tid  = threadIdx.x;
    const int lane = tid & 31;
    const int warp = tid >> 5;                  // 0..3
    const int jj   = warp * 16 + (lane >> 1);   // GRU output unit (pair-split, R13)
    const int kh   = lane & 1;                  // k-half
    const int b0   = blockIdx.x * 2;

    // ---- stage Hp (stride 34, both b) / d0 / wc / vd
    {
        #pragma unroll
        for (int bb = 0; bb < 2; bb++){
            const float* gHp = g_Hp + (size_t)(b0 + bb) * (TT * 32);
            float* Hpb = Hps + bb * (128 * 34);
            for (int i = tid; i < TT * 32; i += 128){
                int tt = i >> 5, a = i & 31;
                Hpb[tt * 34 + a] = gHp[i];
            }
        }
        if (tid < 64){
            dbuf[tid]      = g_d0[(size_t)b0 * 64 + tid];         // buf0, b0
            wc[tid]        = W_out[64 + tid];
        } else {
            dbuf[tid]      = g_d0[(size_t)(b0 + 1) * 64 + (tid - 64)];  // buf0, b1
        }
        if (tid < 32) vd[tid] = v_d[tid];
    }
    __syncthreads();

    // ---- q_t = <wout_c, h_t> for both b's (thread tid = t)
    #pragma unroll
    for (int bb = 0; bb < 2; bb++){
        const ulonglong2* hrow = (const ulonglong2*)(g_H + (size_t)(b0 + bb) * (TT * 64) + (size_t)tid * 64);
        const ulonglong2* wcp  = (const ulonglong2*)wc;
        u64 acc = 0ULL;
        #pragma unroll
        for (int k = 0; k < 16; k++){
            ulonglong2 h2 = hrow[k];
            ulonglong2 w2 = wcp[k];
            fma2(acc, w2.x, h2.x); fma2(acc, w2.y, h2.y);
        }
        qv[bb * 128 + tid] = hsum2(acc);
    }

    // ---- decoder GRU weights: 3 half-rows (pair-split, shared across b's)
    u64 wr[16], wz[16], wn[16];
    {
        const u64* Wr = (const u64*)(W_hh_d + (jj)       * 64 + kh * 32);
        const u64* Wz = (const u64*)(W_hh_d + (64 + jj)  * 64 + kh * 32);
        const u64* Wn = (const u64*)(W_hh_d + (128 + jj) * 64 + kh * 32);
        #pragma unroll
        for (int k = 0; k < 16; k++){ wr[k] = Wr[k]; wz[k] = Wz[k]; wn[k] = Wn[k]; }
    }
    const float wih_r = W_ih_d[jj], wih_z = W_ih_d[64 + jj], wih_n = W_ih_d[128 + jj];
    const float br  = b_ih_d[jj]      + b_hh_d[jj];
    const float bz  = b_ih_d[64 + jj] + b_hh_d[64 + jj];
    const float bin = b_ih_d[128 + jj];
    const float bhn = b_hh_d[128 + jj];
    const float wout_d = W_out[jj];
    const float bo = b_out[0];
    float xd0 = y0[0], xd1 = y0[0];
    __syncthreads();                                   // qv + dbuf visible
    float dj0 = dbuf[jj];                              // buf0, b0 (pair dup)
    float dj1 = dbuf[64 + jj];                         // buf0, b1

    // ---- 24 decoder steps, 4 barriers each (both b's per step)
    for (int s = 0; s < HORZ; s++){
        const float* drow0   = dbuf + (s & 1) * 128;
        const float* drow1   = drow0 + 64;
        float*       drow_n0 = dbuf + ((s + 1) & 1) * 128;
        float*       drow_n1 = drow_n0 + 64;

        // GRU pair-split, both b's
        {
            const ulonglong2* d0p = (const ulonglong2*)(drow0 + kh * 32);
            const ulonglong2* d1p = (const ulonglong2*)(drow1 + kh * 32);
            u64 ar0 = 0ULL, az0 = 0ULL, an0 = 0ULL;
            u64 ar1 = 0ULL, az1 = 0ULL, an1 = 0ULL;
            #pragma unroll
            for (int k = 0; k < 8; k++){
                ulonglong2 a = d0p[k];
                ulonglong2 b = d1p[k];
                fma2(ar0, wr[2*k], a.x); fma2(ar0, wr[2*k+1], a.y);
                fma2(ar1, wr[2*k], b.x); fma2(ar1, wr[2*k+1], b.y);
                fma2(az0, wz[2*k], a.x); fma2(az0, wz[2*k+1], a.y);
                fma2(az1, wz[2*k], b.x); fma2(az1, wz[2*k+1], b.y);
                fma2(an0, wn[2*k], a.x); fma2(an0, wn[2*k+1], a.y);
                fma2(an1, wn[2*k], b.x); fma2(an1, wn[2*k+1], b.y);
            }
            float sr0 = hsum2(ar0); sr0 += __shfl_xor_sync(0xffffffffu, sr0, 1);
            float sz0 = hsum2(az0); sz0 += __shfl_xor_sync(0xffffffffu, sz0, 1);
            float sn0 = hsum2(an0); sn0 += __shfl_xor_sync(0xffffffffu, sn0, 1);
            float sr1 = hsum2(ar1); sr1 += __shfl_xor_sync(0xffffffffu, sr1, 1);
            float sz1 = hsum2(az1); sz1 += __shfl_xor_sync(0xffffffffu, sz1, 1);
            float sn1 = hsum2(an1); sn1 += __shfl_xor_sync(0xffffffffu, sn1, 1);
            float r0 = sigm(fmaf(xd0, wih_r, br) + sr0);
            float r1 = sigm(fmaf(xd1, wih_r, br) + sr1);
            float z0 = sigm(fmaf(xd0, wih_z, bz) + sz0);
            float z1 = sigm(fmaf(xd1, wih_z, bz) + sz1);
            float n0 = tanh_acc(fmaf(xd0, wih_n, bin) + r0 * (sn0 + bhn));
            float n1 = tanh_acc(fmaf(xd1, wih_n, bin) + r1 * (sn1 + bhn));
            dj0 = n0 + z0 * (dj0 - n0);
            dj1 = n1 + z1 * (dj1 - n1);
            drow_n0[jj] = dj0;                         // pair lanes write same value
            drow_n1[jj] = dj1;
            // wsum partials (each j twice per warp -> halve at end)
            float p0 = wout_d * dj0;
            float p1 = wout_d * dj1;
            #pragma unroll
            for (int o = 16; o > 0; o >>= 1){
                p0 += __shfl_xor_sync(0xffffffffu, p0, o);
                p1 += __shfl_xor_sync(0xffffffffu, p1, o);
            }
            if (lane == 0){ red[16 + warp] = p0; red[20 + warp] = p1; }
        }
        __syncthreads();                               // B1: d_new + wsum parts

        // d_proj quarter-split: a = lane, k-quarter = warp, both b's
        {
            const ulonglong2* Wd = (const ulonglong2*)(W_d + lane * 64 + warp * 16);
            const float* s0 = drow_n0 + warp * 16;
            const float* s1 = drow_n1 + warp * 16;
            u64 a0 = 0ULL, a1 = 0ULL;
            #pragma unroll
            for (int k = 0; k < 4; k++){
                ulonglong2 w2 = Wd[k];
                ulonglong2 d0 = *(const ulonglong2*)(s0 + k * 4);
                ulonglong2 d1 = *(const ulonglong2*)(s1 + k * 4);
                fma2(a0, w2.x, d0.x); fma2(a0, w2.y, d0.y);
                fma2(a1, w2.x, d1.x); fma2(a1, w2.y, d1.y);
            }
            cp[warp * 32 + lane]       = hsum2(a0);
            cp[128 + warp * 32 + lane] = hsum2(a1);
        }
        __syncthreads();                               // B2
        if (tid < 64){
            const int bsel = tid >> 5, a = tid & 31;
            const float* c = cp + bsel * 128;
            dpv[bsel * 32 + a] = (c[a] + c[32 + a]) + (c[64 + a] + c[96 + a]);
        }
        __syncthreads();                               // B3

        // scores: thread tid = t, both b's; float2 LDS
        {
            const float2* hp0 = (const float2*)(Hps + tid * 34);
            const float2* hp1 = (const float2*)(Hps + 128 * 34 + tid * 34);
            float sc0 = 0.0f, sc1 = 0.0f;
            #pragma unroll
            for (int k = 0; k < 16; k++){
                float2 vv  = *(const float2*)(vd + 2 * k);        // broadcast
                float2 dp0 = *(const float2*)(dpv + 2 * k);       // broadcast
                float2 dp1 = *(const float2*)(dpv + 32 + 2 * k);  // broadcast
                float2 h0 = hp0[k];
                float2 h1 = hp1[k];
                sc0 = fmaf(vv.x, tanh_fast(dp0.x + h0.x), sc0);
                sc0 = fmaf(vv.y, tanh_fast(dp0.y + h0.y), sc0);
                sc1 = fmaf(vv.x, tanh_fast(dp1.x + h1.x), sc1);
                sc1 = fmaf(vv.y, tanh_fast(dp1.y + h1.y), sc1);
            }
            float e0 = ex2f(sc0 * LOG2E);              // softmax w/o max (bounded)
            float e1 = ex2f(sc1 * LOG2E);
            float q0 = e0 * qv[tid];
            float q1 = e1 * qv[128 + tid];
            #pragma unroll
            for (int o = 16; o > 0; o >>= 1){
                e0 += __shfl_xor_sync(0xffffffffu, e0, o);
                e1 += __shfl_xor_sync(0xffffffffu, e1, o);
                q0 += __shfl_xor_sync(0xffffffffu, q0, o);
                q1 += __shfl_xor_sync(0xffffffffu, q1, o);
            }
            if (lane == 0){
                red[warp]      = e0;
                red[4 + warp]  = e1;
                red[8 + warp]  = q0;
                red[12 + warp] = q1;
            }
        }
        __syncthreads();                               // B4

        float es0 = (red[0] + red[1]) + (red[2] + red[3]);
        float es1 = (red[4] + red[5]) + (red[6] + red[7]);
        float eq0 = (red[8] + red[9]) + (red[10] + red[11]);
        float eq1 = (red[12] + red[13]) + (red[14] + red[15]);
        float ws0 = ((red[16] + red[17]) + (red[18] + red[19])) * 0.5f;
        float ws1 = ((red[20] + red[21]) + (red[22] + red[23])) * 0.5f;
        float v0 = ws0 + bo + eq0 * rcpf(es0);
        float v1 = ws1 + bo + eq1 * rcpf(es1);
        if (tid == 0){
            out[(size_t)b0 * HORZ + s]       = v0;
            out[(size_t)(b0 + 1) * HORZ + s] = v1;
        }
        xd0 = v0;
        xd1 = v1;
    }
}

extern "C" void kernel_launch(void* const* d_in, const int* in_sizes, int n_in,
                              void* d_out, int out_size)
{
    (void)in_sizes; (void)n_in; (void)out_size;
    const float* x      = (const float*)d_in[0];
    const float* W_ih_e = (const float*)d_in[1];
    const float* W_hh_e = (const float*)d_in[2];
    const float* b_ih_e = (const float*)d_in[3];
    const float* b_hh_e = (const float*)d_in[4];
    // d_in[5..8] dead (encoder input attention == softmax over singleton axis)
    const float* W_init = (const float*)d_in[9];
    const float* b_init = (const float*)d_in[10];
    const float* W_ih_d = (const float*)d_in[11];
    const float* W_hh_d = (const float*)d_in[12];
    const float* b_ih_d = (const float*)d_in[13];
    const float* b_hh_d = (const float*)d_in[14];
    const float* W_d    = (const float*)d_in[15];
    const float* U_d    = (const float*)d_in[16];
    const float* v_d    = (const float*)d_in[17];
    const float* W_out  = (const float*)d_in[18];
    const float* b_out  = (const float*)d_in[19];
    const float* y0     = (const float*)d_in[20];
    float* out = (float*)d_out;

    cudaFuncSetAttribute(darnn_enc2, cudaFuncAttributeMaxDynamicSharedMemorySize, E2_BYTES);
    cudaFuncSetAttribute(darnn_dec2, cudaFuncAttributeMaxDynamicSharedMemorySize, DSM_BYTES);

    darnn_enc2<<<2048, 128, E2_BYTES>>>(x, W_ih_e, W_hh_e, b_ih_e, b_hh_e,
                                        W_init, b_init, U_d);
    darnn_dec2<<<2048, 128, DSM_BYTES>>>(W_ih_d, W_hh_d, b_ih_d, b_hh_d,
                                         W_d, v_d, W_out, b_out, y0, out);
}

// round 17
// speedup vs baseline: 1.8574x; 1.0692x over previous
#include <cuda_runtime.h>

#define TT    128
#define HORZ  24
#define LOG2E 1.44269504f

typedef unsigned long long u64;

// ---------------- global scratch (sanctioned __device__ array) ----------------
__device__ float g_H[4096 * TT * 64];    // H[b][t][j]  (h_t at row t)  134 MB

// ---------------- device helpers ----------------
__device__ __forceinline__ void fma2(u64 &acc, u64 w, u64 h){
    asm("fma.rn.f32x2 %0, %1, %2, %0;" : "+l"(acc) : "l"(w), "l"(h));
}
__device__ __forceinline__ float hsum2(u64 a){
    return __uint_as_float((unsigned)a) + __uint_as_float((unsigned)(a >> 32));
}
__device__ __forceinline__ float ex2f(float x){ float y; asm("ex2.approx.f32 %0, %1;" : "=f"(y) : "f"(x)); return y; }
__device__ __forceinline__ float rcpf(float x){ float y; asm("rcp.approx.f32 %0, %1;" : "=f"(y) : "f"(x)); return y; }
__device__ __forceinline__ float sigm(float x){ return rcpf(1.0f + ex2f(-LOG2E * x)); }
__device__ __forceinline__ float tanh_acc(float x){
    float xx = fminf(15.0f, fmaxf(-15.0f, x));
    float e  = ex2f(2.0f * LOG2E * xx);
    return (e - 1.0f) * rcpf(e + 1.0f);
}
__device__ __forceinline__ float tanh_fast(float x){
    float y; asm("tanh.approx.f32 %0, %1;" : "=f"(y) : "f"(x)); return y;
}

// ---------------- fused smem layout (float offsets) ----------------
#define F_HP    0                        // 2 x 128 x 34  (Hp, stride 34)
#define F_XS    (F_HP + 2*128*34)        // 256
#define F_HB    (F_XS + 256)             // 2 bufs x (2 b x 64) h-exchange
#define F_PR    (F_HB + 256)             // 128
#define F_DBUF  (F_PR + 128)             // 2 bufs x 2 b x 64 decoder hidden
#define F_CP    (F_DBUF + 256)           // 2 x 128
#define F_DPV   (F_CP + 256)             // 2 x 32
#define F_VD    (F_DPV + 64)             // 32
#define F_WC    (F_VD + 32)              // 64
#define F_RED   (F_WC + 64)              // 32
#define F_FLOATS (F_RED + 32)
#define F_BYTES  (F_FLOATS * 4)          // ~40.2 KB -> 4 CTAs/SM

extern "C" __global__ void __launch_bounds__(128, 4)
darnn_fused(const float* __restrict__ x,
            const float* __restrict__ W_ih_e, const float* __restrict__ W_hh_e,
            const float* __restrict__ b_ih_e, const float* __restrict__ b_hh_e,
            const float* __restrict__ W_init, const float* __restrict__ b_init,
            const float* __restrict__ W_ih_d, const float* __restrict__ W_hh_d,
            const float* __restrict__ b_ih_d, const float* __restrict__ b_hh_d,
            const float* __restrict__ W_d,    const float* __restrict__ U_d,
            const float* __restrict__ v_d,
            const float* __restrict__ W_out,  const float* __restrict__ b_out,
            const float* __restrict__ y0,
            float* __restrict__ out)
{
    extern __shared__ __align__(16) float sm[];
    float* Hps  = sm + F_HP;              // + bb*4352
    float* xs   = sm + F_XS;
    float* hb   = sm + F_HB;
    float* pR   = sm + F_PR;
    float* dbuf = sm + F_DBUF;            // [buf][b][j]
    float* cp   = sm + F_CP;
    float* dpv  = sm + F_DPV;
    float* vd   = sm + F_VD;
    float* wc   = sm + F_WC;
    float* qv   = pR - 128;               // placeholder (unused name safety)
    float* red  = sm + F_RED;

    const int tid  = threadIdx.x;
    const int lane = tid & 31;
    const int warp = tid >> 5;                  // 0..3
    const int jj   = warp * 16 + (lane >> 1);   // output unit (pair-split)
    const int kh   = lane & 1;                  // k-half
    const int b0   = blockIdx.x * 2;

    // =================== PHASE 1: encoder (verbatim R16 logic) ===============
    u64 wr[16], wz[16], wn[16];
    {
        const u64* Wr = (const u64*)(W_hh_e + (jj)       * 64 + kh * 32);
        const u64* Wz = (const u64*)(W_hh_e + (64 + jj)  * 64 + kh * 32);
        const u64* Wn = (const u64*)(W_hh_e + (128 + jj) * 64 + kh * 32);
        #pragma unroll
        for (int k = 0; k < 16; k++){ wr[k] = Wr[k]; wz[k] = Wz[k]; wn[k] = Wn[k]; }
    }
    {
        const float wih_r = W_ih_e[jj], wih_z = W_ih_e[64 + jj], wih_n = W_ih_e[128 + jj];
        const float br  = b_ih_e[jj]       + b_hh_e[jj];
        const float bz  = b_ih_e[64 + jj]  + b_hh_e[64 + jj];
        const float bin = b_ih_e[128 + jj];
        const float bhn = b_hh_e[128 + jj];

        xs[tid]       = x[(size_t)b0 * TT + tid];
        xs[128 + tid] = x[(size_t)(b0 + 1) * TT + tid];
        hb[tid] = 0.0f;
        if (tid < 32) vd[tid] = v_d[tid];
        if (tid < 64) wc[tid] = W_out[64 + tid];
        __syncthreads();

        float hc0 = 0.0f, hc1 = 0.0f;
        float* gH0 = g_H + (size_t)b0 * (TT * 64) + jj;
        float* gH1 = g_H + (size_t)(b0 + 1) * (TT * 64) + jj;
        for (int t = 0; t < TT; t++){
            const int cur = (t & 1) * 128, nxt = ((t + 1) & 1) * 128;
            const ulonglong2* h0 = (const ulonglong2*)(hb + cur + kh * 32);
            const ulonglong2* h1 = (const ulonglong2*)(hb + cur + 64 + kh * 32);
            u64 ar0 = 0ULL, az0 = 0ULL, an0 = 0ULL;
            u64 ar1 = 0ULL, az1 = 0ULL, an1 = 0ULL;
            #pragma unroll
            for (int k = 0; k < 8; k++){
                ulonglong2 a = h0[k];
                ulonglong2 b = h1[k];
                fma2(ar0, wr[2*k], a.x); fma2(ar0, wr[2*k+1], a.y);
                fma2(ar1, wr[2*k], b.x); fma2(ar1, wr[2*k+1], b.y);
                fma2(az0, wz[2*k], a.x); fma2(az0, wz[2*k+1], a.y);
                fma2(az1, wz[2*k], b.x); fma2(az1, wz[2*k+1], b.y);
                fma2(an0, wn[2*k], a.x); fma2(an0, wn[2*k+1], a.y);
                fma2(an1, wn[2*k], b.x); fma2(an1, wn[2*k+1], b.y);
            }
            float sr0 = hsum2(ar0); sr0 += __shfl_xor_sync(0xffffffffu, sr0, 1);
            float sz0 = hsum2(az0); sz0 += __shfl_xor_sync(0xffffffffu, sz0, 1);
            float sn0 = hsum2(an0); sn0 += __shfl_xor_sync(0xffffffffu, sn0, 1);
            float sr1 = hsum2(ar1); sr1 += __shfl_xor_sync(0xffffffffu, sr1, 1);
            float sz1 = hsum2(az1); sz1 += __shfl_xor_sync(0xffffffffu, sz1, 1);
            float sn1 = hsum2(an1); sn1 += __shfl_xor_sync(0xffffffffu, sn1, 1);
            float xt0 = xs[t], xt1 = xs[128 + t];
            float r0 = sigm(fmaf(xt0, wih_r, br) + sr0);
            float r1 = sigm(fmaf(xt1, wih_r, br) + sr1);
            float z0 = sigm(fmaf(xt0, wih_z, bz) + sz0);
            float z1 = sigm(fmaf(xt1, wih_z, bz) + sz1);
            float n0 = tanh_acc(fmaf(xt0, wih_n, bin) + r0 * (sn0 + bhn));
            float n1 = tanh_acc(fmaf(xt1, wih_n, bin) + r1 * (sn1 + bhn));
            hc0 = n0 + z0 * (hc0 - n0);
            hc1 = n1 + z1 * (hc1 - n1);
            hb[nxt + jj]      = hc0;
            hb[nxt + 64 + jj] = hc1;
            if (kh == 0){                     // pair lanes hold identical values
                gH0[t * 64] = hc0;
                gH1[t * 64] = hc1;
            }
            __syncthreads();
        }
    }

    // ---- H_proj pass from g_H (L2-hot) -> smem Hp (stride 34)
    {
        u64 ud[32];
        const u64* U = (const u64*)(U_d + lane * 64);
        #pragma unroll
        for (int k = 0; k < 32; k++) ud[k] = U[k];
        #pragma unroll
        for (int bb = 0; bb < 2; bb++){
            const float* Hbase = g_H + (size_t)(b0 + bb) * (TT * 64);
            float* Hpb = Hps + bb * (128 * 34);
            for (int tt = 0; tt < 32; tt++){
                int t = warp * 32 + tt;
                const ulonglong2* hrow = (const ulonglong2*)(Hbase + t * 64);
                u64 acc = 0ULL;
                #pragma unroll
                for (int k = 0; k < 16; k++){
                    ulonglong2 h2 = hrow[k];
                    fma2(acc, ud[2*k], h2.x); fma2(acc, ud[2*k+1], h2.y);
                }
                Hpb[t * 34 + lane] = hsum2(acc);
            }
        }
    }

    // ---- d0 = W_init . h_127 + b_init, per b -> dbuf buf0 [b][j]
    {
        const int j2  = ((warp >> 1) << 5) + lane;
        const int kh2 = warp & 1;
        const ulonglong2* Wi = (const ulonglong2*)(W_init + j2 * 64 + kh2 * 32);
        #pragma unroll
        for (int bb = 0; bb < 2; bb++){
            const float* hT = hb + bb * 64 + kh2 * 32;   // buf0 holds h_127
            u64 acc = 0ULL;
            #pragma unroll
            for (int k = 0; k < 8; k++){
                ulonglong2 h2 = *(const ulonglong2*)(hT + k * 4);
                ulonglong2 w2 = Wi[k];
                fma2(acc, w2.x, h2.x); fma2(acc, w2.y, h2.y);
            }
            pR[kh2 * 64 + j2] = hsum2(acc);
            __syncthreads();
            if (kh2 == 0) dbuf[bb * 64 + j2] = pR[j2] + pR[64 + j2] + b_init[j2];
            __syncthreads();
        }
    }

    // ---- qv[b][t] = <wout_c, h_t>  (reuse xs region: encoder xs is dead)
    float* qvv = xs;                      // 256 floats: [b][t]
    #pragma unroll
    for (int bb = 0; bb < 2; bb++){
        const ulonglong2* hrow = (const ulonglong2*)(g_H + (size_t)(b0 + bb) * (TT * 64) + (size_t)tid * 64);
        const ulonglong2* wcp  = (const ulonglong2*)wc;
        u64 acc = 0ULL;
        #pragma unroll
        for (int k = 0; k < 16; k++){
            ulonglong2 h2 = hrow[k];
            ulonglong2 w2 = wcp[k];
            fma2(acc, w2.x, h2.x); fma2(acc, w2.y, h2.y);
        }
        qvv[bb * 128 + tid] = hsum2(acc);
    }

    // =================== PHASE 2: decoder (verbatim R16 dec2 logic) ==========
    {
        const u64* Wr = (const u64*)(W_hh_d + (jj)       * 64 + kh * 32);
        const u64* Wz = (const u64*)(W_hh_d + (64 + jj)  * 64 + kh * 32);
        const u64* Wn = (const u64*)(W_hh_d + (128 + jj) * 64 + kh * 32);
        #pragma unroll
        for (int k = 0; k < 16; k++){ wr[k] = Wr[k]; wz[k] = Wz[k]; wn[k] = Wn[k]; }
    }
    const float wih_r = W_ih_d[jj], wih_z = W_ih_d[64 + jj], wih_n = W_ih_d[128 + jj];
    const float br  = b_ih_d[jj]      + b_hh_d[jj];
    const float bz  = b_ih_d[64 + jj] + b_hh_d[64 + jj];
    const float bin = b_ih_d[128 + jj];
    const float bhn = b_hh_d[128 + jj];
    const float wout_d = W_out[jj];
    const float bo = b_out[0];
    float xd0 = y0[0], xd1 = y0[0];
    __syncthreads();                                   // qv + dbuf + Hp visible
    float dj0 = dbuf[jj];                              // buf0, b0 (pair dup)
    float dj1 = dbuf[64 + jj];                         // buf0, b1

    for (int s = 0; s < HORZ; s++){
        const float* drow0   = dbuf + (s & 1) * 128;
        const float* drow1   = drow0 + 64;
        float*       drow_n0 = dbuf + ((s + 1) & 1) * 128;
        float*       drow_n1 = drow_n0 + 64;

        // GRU pair-split, both b's
        {
            const ulonglong2* d0p = (const ulonglong2*)(drow0 + kh * 32);
            const ulonglong2* d1p = (const ulonglong2*)(drow1 + kh * 32);
            u64 ar0 = 0ULL, az0 = 0ULL, an0 = 0ULL;
            u64 ar1 = 0ULL, az1 = 0ULL, an1 = 0ULL;
            #pragma unroll
            for (int k = 0; k < 8; k++){
                ulonglong2 a = d0p[k];
                ulonglong2 b = d1p[k];
                fma2(ar0, wr[2*k], a.x); fma2(ar0, wr[2*k+1], a.y);
                fma2(ar1, wr[2*k], b.x); fma2(ar1, wr[2*k+1], b.y);
                fma2(az0, wz[2*k], a.x); fma2(az0, wz[2*k+1], a.y);
                fma2(az1, wz[2*k], b.x); fma2(az1, wz[2*k+1], b.y);
                fma2(an0, wn[2*k], a.x); fma2(an0, wn[2*k+1], a.y);
                fma2(an1, wn[2*k], b.x); fma2(an1, wn[2*k+1], b.y);
            }
            float sr0 = hsum2(ar0); sr0 += __shfl_xor_sync(0xffffffffu, sr0, 1);
            float sz0 = hsum2(az0); sz0 += __shfl_xor_sync(0xffffffffu, sz0, 1);
            float sn0 = hsum2(an0); sn0 += __shfl_xor_sync(0xffffffffu, sn0, 1);
            float sr1 = hsum2(ar1); sr1 += __shfl_xor_sync(0xffffffffu, sr1, 1);
            float sz1 = hsum2(az1); sz1 += __shfl_xor_sync(0xffffffffu, sz1, 1);
            float sn1 = hsum2(an1); sn1 += __shfl_xor_sync(0xffffffffu, sn1, 1);
            float r0 = sigm(fmaf(xd0, wih_r, br) + sr0);
            float r1 = sigm(fmaf(xd1, wih_r, br) + sr1);
            float z0 = sigm(fmaf(xd0, wih_z, bz) + sz0);
            float z1 = sigm(fmaf(xd1, wih_z, bz) + sz1);
            float n0 = tanh_acc(fmaf(xd0, wih_n, bin) + r0 * (sn0 + bhn));
            float n1 = tanh_acc(fmaf(xd1, wih_n, bin) + r1 * (sn1 + bhn));
            dj0 = n0 + z0 * (dj0 - n0);
            dj1 = n1 + z1 * (dj1 - n1);
            drow_n0[jj] = dj0;
            drow_n1[jj] = dj1;
            float p0 = wout_d * dj0;
            float p1 = wout_d * dj1;
            #pragma unroll
            for (int o = 16; o > 0; o >>= 1){
                p0 += __shfl_xor_sync(0xffffffffu, p0, o);
                p1 += __shfl_xor_sync(0xffffffffu, p1, o);
            }
            if (lane == 0){ red[16 + warp] = p0; red[20 + warp] = p1; }
        }
        __syncthreads();                               // B1

        // d_proj quarter-split: a = lane, k-quarter = warp, both b's
        {
            const ulonglong2* Wd = (const ulonglong2*)(W_d + lane * 64 + warp * 16);
            const float* s0 = drow_n0 + warp * 16;
            const float* s1 = drow_n1 + warp * 16;
            u64 a0 = 0ULL, a1 = 0ULL;
            #pragma unroll
            for (int k = 0; k < 4; k++){
                ulonglong2 w2 = Wd[k];
                ulonglong2 d0 = *(const ulonglong2*)(s0 + k * 4);
                ulonglong2 d1 = *(const ulonglong2*)(s1 + k * 4);
                fma2(a0, w2.x, d0.x); fma2(a0, w2.y, d0.y);
                fma2(a1, w2.x, d1.x); fma2(a1, w2.y, d1.y);
            }
            cp[warp * 32 + lane]       = hsum2(a0);
            cp[128 + warp * 32 + lane] = hsum2(a1);
        }
        __syncthreads();                               // B2
        if (tid < 64){
            const int bsel = tid >> 5, a = tid & 31;
            const float* c = cp + bsel * 128;
            dpv[bsel * 32 + a] = (c[a] + c[32 + a]) + (c[64 + a] + c[96 + a]);
        }
        __syncthreads();                               // B3

        // scores: thread tid = t, both b's; float2 LDS
        {
            const float2* hp0 = (const float2*)(Hps + tid * 34);
            const float2* hp1 = (const float2*)(Hps + 128 * 34 + tid * 34);
            float sc0 = 0.0f, sc1 = 0.0f;
            #pragma unroll
            for (int k = 0; k < 16; k++){
                float2 vv  = *(const float2*)(vd + 2 * k);
                float2 dp0 = *(const float2*)(dpv + 2 * k);
                float2 dp1 = *(const float2*)(dpv + 32 + 2 * k);
                float2 h0 = hp0[k];
                float2 h1 = hp1[k];
                sc0 = fmaf(vv.x, tanh_fast(dp0.x + h0.x), sc0);
                sc0 = fmaf(vv.y, tanh_fast(dp0.y + h0.y), sc0);
                sc1 = fmaf(vv.x, tanh_fast(dp1.x + h1.x), sc1);
                sc1 = fmaf(vv.y, tanh_fast(dp1.y + h1.y), sc1);
            }
            float e0 = ex2f(sc0 * LOG2E);
            float e1 = ex2f(sc1 * LOG2E);
            float q0 = e0 * qvv[tid];
            float q1 = e1 * qvv[128 + tid];
            #pragma unroll
            for (int o = 16; o > 0; o >>= 1){
                e0 += __shfl_xor_sync(0xffffffffu, e0, o);
                e1 += __shfl_xor_sync(0xffffffffu, e1, o);
                q0 += __shfl_xor_sync(0xffffffffu, q0, o);
                q1 += __shfl_xor_sync(0xffffffffu, q1, o);
            }
            if (lane == 0){
                red[warp]      = e0;
                red[4 + warp]  = e1;
                red[8 + warp]  = q0;
                red[12 + warp] = q1;
            }
        }
        __syncthreads();                               // B4

        float es0 = (red[0] + red[1]) + (red[2] + red[3]);
        float es1 = (red[4] + red[5]) + (red[6] + red[7]);
        float eq0 = (red[8] + red[9]) + (red[10] + red[11]);
        float eq1 = (red[12] + red[13]) + (red[14] + red[15]);
        float ws0 = ((red[16] + red[17]) + (red[18] + red[19])) * 0.5f;
        float ws1 = ((red[20] + red[21]) + (red[22] + red[23])) * 0.5f;
        float v0 = ws0 + bo + eq0 * rcpf(es0);
        float v1 = ws1 + bo + eq1 * rcpf(es1);
        if (tid == 0){
            out[(size_t)b0 * HORZ + s]       = v0;
            out[(size_t)(b0 + 1) * HORZ + s] = v1;
        }
        xd0 = v0;
        xd1 = v1;
    }
}

extern "C" void kernel_launch(void* const* d_in, const int* in_sizes, int n_in,
                              void* d_out, int out_size)
{
    (void)in_sizes; (void)n_in; (void)out_size;
    const float* x      = (const float*)d_in[0];
    const float* W_ih_e = (const float*)d_in[1];
    const float* W_hh_e = (const float*)d_in[2];
    const float* b_ih_e = (const float*)d_in[3];
    const float* b_hh_e = (const float*)d_in[4];
    // d_in[5..8] dead (encoder input attention == softmax over singleton axis)
    const float* W_init = (const float*)d_in[9];
    const float* b_init = (const float*)d_in[10];
    const float* W_ih_d = (const float*)d_in[11];
    const float* W_hh_d = (const float*)d_in[12];
    const float* b_ih_d = (const float*)d_in[13];
    const float* b_hh_d = (const float*)d_in[14];
    const float* W_d    = (const float*)d_in[15];
    const float* U_d    = (const float*)d_in[16];
    const float* v_d    = (const float*)d_in[17];
    const float* W_out  = (const float*)d_in[18];
    const float* b_out  = (const float*)d_in[19];
    const float* y0     = (const float*)d_in[20];
    float* out = (float*)d_out;

    cudaFuncSetAttribute(darnn_fused, cudaFuncAttributeMaxDynamicSharedMemorySize, F_BYTES);

    darnn_fused<<<2048, 128, F_BYTES>>>(x, W_ih_e, W_hh_e, b_ih_e, b_hh_e,
                                        W_init, b_init,
                                        W_ih_d, W_hh_d, b_ih_d, b_hh_d,
                                        W_d, U_d, v_d, W_out, b_out, y0, out);
}